// round 12
// baseline (speedup 1.0000x reference)
#include <cuda_runtime.h>
#include <cuda_fp16.h>
#include <cuda_fp8.h>
#include <math.h>
#include <stdint.h>

#define D_HIDDEN 1024
#define D_INTER  4096
#define NE       8
#define NTOK     2048
#define NPAIR    (NTOK * 2)
#define GU_ROWS  8192

// gemm1 per-buffer: AH 16K | AL8 8K | BH 16K | BL8 8K = 48K; gemm2: AH 16K | B @32K
#define SM_AH    0
#define SM_AL8   16384
#define SM_BH    24576
#define SM_BB    32768
#define SM_BL8   40960
#define SM_BUF   49152
#define SM_TOK   98304
#define SM_COEF  98816
#define SM_TOTAL 99328

__device__ __forceinline__ uint32_t smem_u32(const void* p) {
    uint32_t a;
    asm("{ .reg .u64 t; cvta.to.shared.u64 t, %1; cvt.u32.u64 %0, t; }" : "=r"(a) : "l"(p));
    return a;
}
#define LDSM_X4(r, addr) \
    asm volatile("ldmatrix.sync.aligned.m8n8.x4.shared.b16 {%0,%1,%2,%3}, [%4];" \
        : "=r"((r)[0]), "=r"((r)[1]), "=r"((r)[2]), "=r"((r)[3]) : "r"(addr))
#define MMAF16(c, a, b0, b1) \
    asm volatile("mma.sync.aligned.m16n8k16.row.col.f32.f16.f16.f32 " \
        "{%0,%1,%2,%3}, {%4,%5,%6,%7}, {%8,%9}, {%0,%1,%2,%3};" \
        : "+f"((c)[0]), "+f"((c)[1]), "+f"((c)[2]), "+f"((c)[3]) \
        : "r"((a)[0]), "r"((a)[1]), "r"((a)[2]), "r"((a)[3]), "r"(b0), "r"(b1))
#define MMAF8(c, a, b0, b1) \
    asm volatile("mma.sync.aligned.m16n8k32.row.col.f32.e4m3.e4m3.f32 " \
        "{%0,%1,%2,%3}, {%4,%5,%6,%7}, {%8,%9}, {%0,%1,%2,%3};" \
        : "+f"((c)[0]), "+f"((c)[1]), "+f"((c)[2]), "+f"((c)[3]) \
        : "r"((a)[0]), "r"((a)[1]), "r"((a)[2]), "r"((a)[3]), "r"(b0), "r"(b1))
#define CP16(dst, src) \
    asm volatile("cp.async.cg.shared.global [%0], [%1], 16;" :: "r"(dst), "l"(src))
#define CP_COMMIT() asm volatile("cp.async.commit_group;" ::: "memory")
#define CP_WAIT0()  asm volatile("cp.async.wait_group 0;" ::: "memory")

// fp4 pair -> packed fp16x2 (exact); adjc = 0x3800 + (s-127)<<10
__device__ __forceinline__ uint32_t dq16(uint32_t byte, uint32_t adjc) {
    uint32_t n0 = byte & 15u, n1 = (byte >> 4) & 15u;
    uint32_t m0 = n0 & 7u, m1 = n1 & 7u;
    uint32_t b0 = (m0 == 0u) ? 0u : (adjc + ((m0 >= 2u) ? (m0 << 9) : 0u));
    uint32_t b1 = (m1 == 0u) ? 0u : (adjc + ((m1 >= 2u) ? (m1 << 9) : 0u));
    b0 |= (n0 & 8u) << 12;  b1 |= (n1 & 8u) << 12;
    return b0 | (b1 << 16);
}
// fp4 nibble + scale s -> e4m3 bits of w = mant * 2^(s-127)
__device__ __forceinline__ uint32_t dqf8(uint32_t nib, int s) {
    uint32_t m2 = (0xC8643210u >> ((nib & 7u) * 4)) & 15u;  // 2*mant
    uint32_t sign = (nib & 8u) << 4;
    if (m2 == 0u) return sign;
    int p = 31 - __clz((int)m2);          // 0..3
    int ebits = p + s - 121;              // exponent field
    uint32_t bits;
    if (ebits >= 1) {
        bits = ((uint32_t)ebits << 3) | ((m2 << (3 - p)) & 7u);
        if (bits > 0x7Eu) bits = 0x7Eu;   // clamp (can't trigger for s<=132)
    } else {
        int sh = s - 119;                 // subnormal k = round(m2 * 2^sh)
        uint32_t k = (sh >= 0) ? (m2 << sh) : ((m2 + (1u << (-sh - 1))) >> (-sh));
        bits = (k > 7u) ? 7u : k;
    }
    return bits | sign;
}

__device__ int   g_top_idx[NTOK][2];
__device__ float g_top_w[NTOK][2];
__device__ int   g_count[NE];
__device__ int   g_off[NE];
__device__ int   g_list[NE][NTOK];
__device__ float g_coefs[NE][NTOK];
__device__ unsigned short g_x_h[(size_t)NTOK * D_HIDDEN];
__device__ unsigned char  g_x_l8[(size_t)NTOK * D_HIDDEN];
__device__ unsigned short g_act[(size_t)NPAIR * D_INTER];
__device__ uint4 g_gu_pack[(size_t)NE * GU_ROWS * 32];
__device__ uint4 g_dn_pack[(size_t)NE * D_HIDDEN * 128];
__device__ uint2 g_wlo8[(size_t)NE * GU_ROWS * 128];   // e4m3 gu weights, 1 B/elem

__global__ void zero_kernel(float* __restrict__ out, int n) {
    int i = blockIdx.x * blockDim.x + threadIdx.x;
    if (i < n) out[i] = 0.0f;
}
// x -> fp16 hi + e4m3 residual (scale 2^12)
__global__ void prep_x_kernel(const float* __restrict__ x) {
    int row = blockIdx.x;
    int c = threadIdx.x * 4;
    float4 f = *(const float4*)(x + (size_t)row * D_HIDDEN + c);
    float v[4] = {f.x, f.y, f.z, f.w};
    unsigned short h[4]; uint32_t l8 = 0;
#pragma unroll
    for (int i = 0; i < 4; i++) {
        __half hh = __float2half_rn(v[i]);
        h[i] = __half_as_ushort(hh);
        float r = (v[i] - __half2float(hh)) * 4096.0f;
        unsigned char b = (unsigned char)__nv_cvt_float_to_fp8(r, __NV_SATFINITE, __NV_E4M3);
        l8 |= (uint32_t)b << (i * 8);
    }
    uint2 ph;
    ph.x = (uint32_t)h[0] | ((uint32_t)h[1] << 16);
    ph.y = (uint32_t)h[2] | ((uint32_t)h[3] << 16);
    *(uint2*)(g_x_h + (size_t)row * D_HIDDEN + c) = ph;
    *(uint32_t*)(g_x_l8 + (size_t)row * D_HIDDEN + c) = l8;
}
__global__ void pack_kernel(const int* __restrict__ src, uint4* __restrict__ dst) {
    size_t i = (size_t)blockIdx.x * 256 + threadIdx.x;
    const int4* s = (const int4*)src + i * 4;
    int4 a = s[0], b = s[1], c = s[2], d = s[3];
    uint4 o;
    o.x = (a.x & 255) | ((a.y & 255) << 8) | ((a.z & 255) << 16) | ((a.w & 255) << 24);
    o.y = (b.x & 255) | ((b.y & 255) << 8) | ((b.z & 255) << 16) | ((b.w & 255) << 24);
    o.z = (c.x & 255) | ((c.y & 255) << 8) | ((c.z & 255) << 16) | ((c.w & 255) << 24);
    o.w = (d.x & 255) | ((d.y & 255) << 8) | ((d.z & 255) << 16) | ((d.w & 255) << 24);
    dst[i] = o;
}
// gu weights -> e4m3 bytes (direct value, no row scale)
__global__ void prep_wlo8_kernel(const int* __restrict__ gus) {
    size_t g = (size_t)blockIdx.x * 256 + threadIdx.x;   // 8.4M threads
    size_t row = g >> 7;                                  // 128 thr/row
    uint32_t within = (uint32_t)(g & 127);
    uint32_t w = ((const uint32_t*)g_gu_pack)[row * 128 + within];
    int s = gus[row * 32 + (within >> 2)];
    uint32_t o0 = 0, o1 = 0;
#pragma unroll
    for (int b = 0; b < 4; b++) {
        uint32_t byte = (w >> (8 * b)) & 255u;
        uint32_t p = dqf8(byte & 15u, s) | (dqf8(byte >> 4, s) << 8);
        if (b < 2) o0 |= p << (16 * b); else o1 |= p << (16 * (b - 2));
    }
    g_wlo8[g] = make_uint2(o0, o1);
}
__global__ void router_kernel(const float* __restrict__ x,
                              const float* __restrict__ rw,
                              const float* __restrict__ rb) {
    int warp = threadIdx.x >> 5, lane = threadIdx.x & 31;
    int t = blockIdx.x * 8 + warp;
    if (t >= NTOK) return;
    float acc[NE];
#pragma unroll
    for (int e = 0; e < NE; e++) acc[e] = 0.0f;
    const float* xr = x + (size_t)t * D_HIDDEN;
    for (int k = lane; k < D_HIDDEN; k += 32) {
        float xv = xr[k];
#pragma unroll
        for (int e = 0; e < NE; e++) acc[e] += xv * rw[e * D_HIDDEN + k];
    }
#pragma unroll
    for (int e = 0; e < NE; e++)
#pragma unroll
        for (int o = 16; o > 0; o >>= 1) acc[e] += __shfl_xor_sync(0xffffffffu, acc[e], o);
    if (lane == 0) {
        float v[NE];
#pragma unroll
        for (int e = 0; e < NE; e++) v[e] = acc[e] + rb[e];
        int i0 = 0;
#pragma unroll
        for (int e = 1; e < NE; e++) if (v[e] > v[i0]) i0 = e;
        int i1 = -1;
#pragma unroll
        for (int e = 0; e < NE; e++) {
            if (e == i0) continue;
            if (i1 < 0 || v[e] > v[i1]) i1 = e;
        }
        float w1 = expf(v[i1] - v[i0]);
        float inv = 1.0f / (1.0f + w1);
        g_top_idx[t][0] = i0; g_top_idx[t][1] = i1;
        g_top_w[t][0] = inv;  g_top_w[t][1] = w1 * inv;
    }
}
__global__ void compact_kernel() {
    const int e = blockIdx.x, tid = threadIdx.x;
    __shared__ int scan[256];
    __shared__ int sbase;
    if (tid == 0) sbase = 0;
    __syncthreads();
    for (int c = 0; c < NTOK; c += 256) {
        int t = c + tid;
        int flag = (g_top_idx[t][0] == e) || (g_top_idx[t][1] == e);
        float coef = (g_top_idx[t][0] == e) ? g_top_w[t][0] : g_top_w[t][1];
        scan[tid] = flag;
        __syncthreads();
#pragma unroll
        for (int off = 1; off < 256; off <<= 1) {
            int v = (tid >= off) ? scan[tid - off] : 0;
            __syncthreads();
            scan[tid] += v;
            __syncthreads();
        }
        if (flag) {
            int pos = sbase + scan[tid] - 1;
            g_list[e][pos] = t; g_coefs[e][pos] = coef;
        }
        __syncthreads();
        if (tid == 0) sbase += scan[255];
        __syncthreads();
    }
    if (tid == 0) g_count[e] = sbase;
}
__global__ void offsets_kernel() {
    if (threadIdx.x == 0) {
        int r = 0;
#pragma unroll
        for (int e = 0; e < NE; e++) { g_off[e] = r; r += g_count[e]; }
    }
}

// ============================================================
// GEMM1: fp16 hi plane + e4m3 residual plane. 128x128, BK=64,
// 8 warps (4M x 2N), warp 32x64, double-buffered cp.async, occ1.
// ============================================================
__global__ __launch_bounds__(256, 1) void gemm1_kernel(
    const int* __restrict__ gus, const float* __restrict__ gbias) {
    const int e  = blockIdx.y >> 6;
    const int r0 = (blockIdx.y & 63) << 7;
    const int m0 = blockIdx.x << 7;
    const int cnt = g_count[e];
    if (m0 >= cnt) return;
    const int valid = min(128, cnt - m0);
    const int off = g_off[e];
    extern __shared__ char smem[];
    const uint32_t sb = smem_u32(smem);
    const int tid = threadIdx.x, wid = tid >> 5, lane = tid & 31;
    const int wm = wid & 3, wn = wid >> 2;

    int* stok = (int*)(smem + SM_TOK);
    if (tid < 128) stok[tid] = g_list[e][m0 + (tid < valid ? tid : 0)];
    __syncthreads();

    const int arow = tid >> 1, kh = (tid & 1) << 5;
    const unsigned short* xh = g_x_h + (size_t)stok[arow] * D_HIDDEN + kh;
    const unsigned char* xl8 = g_x_l8 + (size_t)stok[arow] * D_HIDDEN + kh;   // bytes, kh elems
    const uint4* bw = g_gu_pack + (size_t)(e * GU_ROWS + r0 + arow) * 32;
    const int*  sc = gus + (size_t)(e * GU_ROWS + r0 + arow) * 32;
    const unsigned char* bl8 = (const unsigned char*)g_wlo8 + (size_t)(e * GU_ROWS + r0 + arow) * 1024 + kh;
    const uint32_t fbase = (uint32_t)arow << 7;
    const uint32_t frx = ((uint32_t)arow & 7u) << 4;
    uint32_t fo[4];
#pragma unroll
    for (int j = 0; j < 4; j++)
        fo[j] = fbase + ((((uint32_t)(kh + j * 8)) << 1) ^ frx);
    const uint32_t frxL = (((uint32_t)arow >> 1) & 3u) << 4;
    uint32_t fo8[2];
#pragma unroll
    for (int j = 0; j < 2; j++)
        fo8[j] = (uint32_t)arow * 64u + (((uint32_t)(kh + j * 16)) ^ frxL);

    uint32_t aAddr[2], arx[2], aAddrL[2], arxL[2];
#pragma unroll
    for (int mf = 0; mf < 2; mf++) {
        int r = wm * 32 + mf * 16 + (lane & 15);
        aAddr[mf] = sb + SM_AH + ((uint32_t)r << 7);
        arx[mf] = ((uint32_t)r & 7u) << 4;
        aAddrL[mf] = sb + SM_AL8 + (uint32_t)r * 64u;
        arxL[mf] = (((uint32_t)r >> 1) & 3u) << 4;
    }
    const uint32_t a_cb = (uint32_t)(lane >> 4) << 4;
    uint32_t bAddr[4], brxv[4], bAddrL[4], brxL[4];
#pragma unroll
    for (int g = 0; g < 4; g++) {
        int r = wn * 64 + g * 16 + ((lane >> 4) << 3) + (lane & 7);
        bAddr[g] = sb + SM_BH + ((uint32_t)r << 7);
        brxv[g] = ((uint32_t)r & 7u) << 4;
        bAddrL[g] = sb + SM_BL8 + (uint32_t)r * 64u;
        brxL[g] = (((uint32_t)r >> 1) & 3u) << 4;
    }
    const uint32_t b_cb = ((uint32_t)(lane >> 3) & 1u) << 4;

    float acc[2][8][4], accl[2][8][4];
#pragma unroll
    for (int mf = 0; mf < 2; mf++)
#pragma unroll
        for (int nf = 0; nf < 8; nf++)
#pragma unroll
            for (int j = 0; j < 4; j++) { acc[mf][nf][j] = 0.0f; accl[mf][nf][j] = 0.0f; }

    // prologue: async A-hi/A-lo/B-lo chunk0; B-hi regs chunk0
#pragma unroll
    for (int j = 0; j < 4; j++) CP16(sb + SM_AH + fo[j], xh + j * 8);
#pragma unroll
    for (int j = 0; j < 2; j++) {
        CP16(sb + SM_AL8 + fo8[j], xl8 + j * 16);
        CP16(sb + SM_BL8 + fo8[j], bl8 + j * 16);
    }
    CP_COMMIT();
    uint4 ub = bw[tid & 1];
    uint32_t adj = 0x3800u + (uint32_t)((sc[tid & 1] - 127) << 10);

    const int NKB = D_HIDDEN / 64;
    for (int kb = 0; kb < NKB; kb++) {
        const uint32_t bo = (uint32_t)(kb & 1) * SM_BUF;
        {   // B-hi dequant from prefetched regs
            uint32_t w4[4] = {ub.x, ub.y, ub.z, ub.w};
#pragma unroll
            for (int q = 0; q < 4; q++) {
                uint32_t ww = w4[q];
                uint4 r;
                r.x = dq16(ww & 255u, adj);
                r.y = dq16((ww >> 8) & 255u, adj);
                r.z = dq16((ww >> 16) & 255u, adj);
                r.w = dq16(ww >> 24, adj);
                *(uint4*)(smem + bo + SM_BH + fo[q]) = r;
            }
        }
        CP_WAIT0();
        __syncthreads();
        if (kb + 1 < NKB) {
            const uint32_t bo2 = (uint32_t)((kb + 1) & 1) * SM_BUF;
#pragma unroll
            for (int j = 0; j < 4; j++) CP16(sb + bo2 + SM_AH + fo[j], xh + (kb + 1) * 64 + j * 8);
#pragma unroll
            for (int j = 0; j < 2; j++) {
                CP16(sb + bo2 + SM_AL8 + fo8[j], xl8 + (kb + 1) * 64 + j * 16);
                CP16(sb + bo2 + SM_BL8 + fo8[j], bl8 + (kb + 1) * 64 + j * 16);
            }
            CP_COMMIT();
            int bin = (kb + 1) * 2 + (tid & 1);
            ub = bw[bin];
            adj = 0x3800u + (uint32_t)((sc[bin] - 127) << 10);
        }
        // hi plane: fp16 k16 x4
#pragma unroll
        for (int ks = 0; ks < 4; ks++) {
            uint32_t acol = (uint32_t)ks * 32 + a_cb;
            uint32_t bcol = (uint32_t)ks * 32 + b_cb;
            uint32_t Ah[2][4], Bf[4][4];
#pragma unroll
            for (int mf = 0; mf < 2; mf++) LDSM_X4(Ah[mf], aAddr[mf] + bo + (acol ^ arx[mf]));
#pragma unroll
            for (int g = 0; g < 4; g++) LDSM_X4(Bf[g], bAddr[g] + bo + (bcol ^ brxv[g]));
#pragma unroll
            for (int mf = 0; mf < 2; mf++)
#pragma unroll
                for (int nf = 0; nf < 8; nf++)
                    MMAF16(acc[mf][nf], Ah[mf], Bf[nf >> 1][(nf & 1) * 2], Bf[nf >> 1][(nf & 1) * 2 + 1]);
        }
        // lo plane: e4m3 k32 x2
#pragma unroll
        for (int ki = 0; ki < 2; ki++) {
            uint32_t acol = (uint32_t)ki * 32 + a_cb;
            uint32_t bcol = (uint32_t)ki * 32 + b_cb;
            uint32_t Ai[2][4], Bi[4][4];
#pragma unroll
            for (int mf = 0; mf < 2; mf++) LDSM_X4(Ai[mf], aAddrL[mf] + bo + (acol ^ arxL[mf]));
#pragma unroll
            for (int g = 0; g < 4; g++) LDSM_X4(Bi[g], bAddrL[g] + bo + (bcol ^ brxL[g]));
#pragma unroll
            for (int mf = 0; mf < 2; mf++)
#pragma unroll
                for (int nf = 0; nf < 8; nf++)
                    MMAF8(accl[mf][nf], Ai[mf], Bi[nf >> 1][(nf & 1) * 2], Bi[nf >> 1][(nf & 1) * 2 + 1]);
        }
    }
    __syncthreads();

    // epilogue: combine planes + bias + SwiGLU -> fp16 act
    const float LSC = 1.0f / 4096.0f;
    const float* gb = gbias + (size_t)e * GU_ROWS;
    unsigned short* stage = (unsigned short*)smem;
#pragma unroll
    for (int mf = 0; mf < 2; mf++)
#pragma unroll
        for (int nf = 0; nf < 8; nf++) {
            int gucol = r0 + wn * 64 + nf * 8 + (lane & 3) * 2;
            float bg = gb[gucol], bu = gb[gucol + 1];
            int cl = wn * 32 + nf * 4 + (lane & 3);
#pragma unroll
            for (int rr = 0; rr < 2; rr++) {
                int r = wm * 32 + mf * 16 + (lane >> 2) + rr * 8;
                float gate = acc[mf][nf][rr * 2 + 0] + accl[mf][nf][rr * 2 + 0] * LSC + bg;
                float up   = acc[mf][nf][rr * 2 + 1] + accl[mf][nf][rr * 2 + 1] * LSC + bu;
                gate = fminf(gate, 7.0f);
                up = fminf(fmaxf(up, -7.0f), 7.0f);
                float sg = 1.0f / (1.0f + __expf(-1.702f * gate));
                float a = (up + 1.0f) * (gate * sg);
                stage[r * 72 + cl] = __half_as_ushort(__float2half_rn(a));
            }
        }
    __syncthreads();
    {
        int row = tid >> 1;
        if (row < valid) {
            size_t gbase = (size_t)(off + m0 + row) * D_INTER + (r0 >> 1) + (tid & 1) * 32;
            uint4* dh = (uint4*)(g_act + gbase);
            const uint4* shp = (const uint4*)(stage + row * 72 + (tid & 1) * 32);
#pragma unroll
            for (int i = 0; i < 4; i++) dh[i] = shp[i];
        }
    }
}

// ============================================================
// GEMM2 (single fp16 plane) — unchanged from R11.
// ============================================================
__global__ __launch_bounds__(256, 2) void gemm2_kernel(
    const int* __restrict__ dns, const float* __restrict__ dbias,
    float* __restrict__ out) {
    const int e  = blockIdx.y >> 3;
    const int r0 = (blockIdx.y & 7) << 7;
    const int m0 = blockIdx.x << 7;
    const int cnt = g_count[e];
    if (m0 >= cnt) return;
    const int valid = min(128, cnt - m0);
    const int off = g_off[e];
    extern __shared__ char smem[];
    const uint32_t sb = smem_u32(smem);
    const int tid = threadIdx.x, wid = tid >> 5, lane = tid & 31;
    const int wm = wid & 3, wn = wid >> 2;

    int* stok = (int*)(smem + SM_TOK);
    float* scoef = (float*)(smem + SM_COEF);
    if (tid < 128) {
        int mm = (tid < valid) ? tid : 0;
        stok[tid] = g_list[e][m0 + mm];
        scoef[tid] = g_coefs[e][m0 + mm];
    }
    __syncthreads();

    const int arow = tid >> 1, kh = (tid & 1) << 5;
    const int pr = off + m0 + ((arow < valid) ? arow : 0);
    const unsigned short* ah = g_act + (size_t)pr * D_INTER + kh;
    const uint4* bw = g_dn_pack + (size_t)(e * D_HIDDEN + r0 + arow) * 128;
    const int*  sc = dns + (size_t)(e * D_HIDDEN + r0 + arow) * 128;
    const uint32_t fbase = (uint32_t)arow << 7;
    const uint32_t frx = ((uint32_t)arow & 7u) << 4;
    uint32_t fo[4];
#pragma unroll
    for (int j = 0; j < 4; j++)
        fo[j] = fbase + ((((uint32_t)(kh + j * 8)) << 1) ^ frx);

    uint32_t aAddr[2], arx[2];
#pragma unroll
    for (int mf = 0; mf < 2; mf++) {
        int r = wm * 32 + mf * 16 + (lane & 15);
        aAddr[mf] = sb + ((uint32_t)r << 7);
        arx[mf] = ((uint32_t)r & 7u) << 4;
    }
    const uint32_t a_cb = (uint32_t)(lane >> 4) << 4;
    uint32_t bAddr[4], brxv[4];
#pragma unroll
    for (int g = 0; g < 4; g++) {
        int r = wn * 64 + g * 16 + ((lane >> 4) << 3) + (lane & 7);
        bAddr[g] = sb + SM_BB + ((uint32_t)r << 7);
        brxv[g] = ((uint32_t)r & 7u) << 4;
    }
    const uint32_t b_cb = ((uint32_t)(lane >> 3) & 1u) << 4;

    float acc[2][8][4];
#pragma unroll
    for (int mf = 0; mf < 2; mf++)
#pragma unroll
        for (int nf = 0; nf < 8; nf++)
#pragma unroll
            for (int j = 0; j < 4; j++) acc[mf][nf][j] = 0.0f;

#pragma unroll
    for (int j = 0; j < 4; j++) CP16(sb + SM_AH + fo[j], ah + j * 8);
    CP_COMMIT();
    uint4 ub = bw[tid & 1];
    uint32_t adj = 0x3800u + (uint32_t)((sc[tid & 1] - 127) << 10);

    const int NKB = D_INTER / 64;
    for (int kb = 0; kb < NKB; kb++) {
        const uint32_t bo = (uint32_t)(kb & 1) * SM_BUF;
        {
            uint32_t w4[4] = {ub.x, ub.y, ub.z, ub.w};
#pragma unroll
            for (int q = 0; q < 4; q++) {
                uint32_t ww = w4[q];
                uint4 r;
                r.x = dq16(ww & 255u, adj);
                r.y = dq16((ww >> 8) & 255u, adj);
                r.z = dq16((ww >> 16) & 255u, adj);
                r.w = dq16(ww >> 24, adj);
                *(uint4*)(smem + bo + SM_BB + fo[q]) = r;
            }
        }
        CP_WAIT0();
        __syncthreads();
        if (kb + 1 < NKB) {
            const uint32_t bo2 = (uint32_t)((kb + 1) & 1) * SM_BUF;
#pragma unroll
            for (int j = 0; j < 4; j++)
                CP16(sb + bo2 + SM_AH + fo[j], ah + (kb + 1) * 64 + j * 8);
            CP_COMMIT();
            int bin = (kb + 1) * 2 + (tid & 1);
            ub = bw[bin];
            adj = 0x3800u + (uint32_t)((sc[bin] - 127) << 10);
        }
#pragma unroll
        for (int ks = 0; ks < 4; ks++) {
            uint32_t acol = (uint32_t)ks * 32 + a_cb;
            uint32_t bcol = (uint32_t)ks * 32 + b_cb;
            uint32_t Ah[2][4], Bf[4][4];
#pragma unroll
            for (int mf = 0; mf < 2; mf++)
                LDSM_X4(Ah[mf], aAddr[mf] + bo + SM_AH + (acol ^ arx[mf]));
#pragma unroll
            for (int g = 0; g < 4; g++) LDSM_X4(Bf[g], bAddr[g] + bo + (bcol ^ brxv[g]));
#pragma unroll
            for (int mf = 0; mf < 2; mf++)
#pragma unroll
                for (int nf = 0; nf < 8; nf++) {
                    uint32_t bb0 = Bf[nf >> 1][(nf & 1) * 2];
                    uint32_t bb1 = Bf[nf >> 1][(nf & 1) * 2 + 1];
                    MMAF16(acc[mf][nf], Ah[mf], bb0, bb1);
                }
        }
    }

    const float* db = dbias + (size_t)e * D_HIDDEN;
#pragma unroll
    for (int mf = 0; mf < 2; mf++)
#pragma unroll
        for (int nf = 0; nf < 8; nf++) {
            int gcol = r0 + wn * 64 + nf * 8 + (lane & 3) * 2;
            float b0 = db[gcol], b1 = db[gcol + 1];
#pragma unroll
            for (int rr = 0; rr < 2; rr++) {
                int m = wm * 32 + mf * 16 + (lane >> 2) + rr * 8;
                if (m < valid) {
                    float coef = scoef[m];
                    float* orow = out + (size_t)stok[m] * D_HIDDEN;
                    atomicAdd(orow + gcol,     coef * (acc[mf][nf][rr * 2 + 0] + b0));
                    atomicAdd(orow + gcol + 1, coef * (acc[mf][nf][rr * 2 + 1] + b1));
                }
            }
        }
}

// ============================================================
extern "C" void kernel_launch(void* const* d_in, const int* in_sizes, int n_in,
                              void* d_out, int out_size) {
    const float* x     = (const float*)d_in[0];
    const float* rw    = (const float*)d_in[1];
    const float* rb    = (const float*)d_in[2];
    const float* gbias = (const float*)d_in[3];
    const float* dbias = (const float*)d_in[4];
    const int*   gub   = (const int*)d_in[5];
    const int*   gus   = (const int*)d_in[6];
    const int*   dnb   = (const int*)d_in[7];
    const int*   dns   = (const int*)d_in[8];
    float* out = (float*)d_out;

    cudaFuncSetAttribute(gemm1_kernel, cudaFuncAttributeMaxDynamicSharedMemorySize, SM_TOTAL);
    cudaFuncSetAttribute(gemm2_kernel, cudaFuncAttributeMaxDynamicSharedMemorySize, SM_TOTAL);
    uint4* gu_pack; cudaGetSymbolAddress((void**)&gu_pack, g_gu_pack);
    uint4* dn_pack; cudaGetSymbolAddress((void**)&dn_pack, g_dn_pack);

    zero_kernel<<<(out_size + 255) / 256, 256>>>(out, out_size);
    prep_x_kernel<<<NTOK, 256>>>(x);
    pack_kernel<<<8192, 256>>>(gub, gu_pack);
    pack_kernel<<<4096, 256>>>(dnb, dn_pack);
    prep_wlo8_kernel<<<32768, 256>>>(gus);
    router_kernel<<<NTOK / 8, 256>>>(x, rw, rb);
    compact_kernel<<<NE, 256>>>();
    offsets_kernel<<<1, 32>>>();
    gemm1_kernel<<<dim3(16, NE * 64), 256, SM_TOTAL>>>(gus, gbias);
    gemm2_kernel<<<dim3(16, NE * 8), 256, SM_TOTAL>>>(dns, dbias, out);
}

// round 14
// speedup vs baseline: 1.3532x; 1.3532x over previous
#include <cuda_runtime.h>
#include <cuda_fp16.h>
#include <math.h>
#include <stdint.h>

#define D_HIDDEN 1024
#define D_INTER  4096
#define NE       8
#define NTOK     2048
#define NPAIR    (NTOK * 2)
#define GU_ROWS  8192

// per-buffer: AH 16K | AL 16K | B 16K ; two buffers (stride 48K)
#define SM_AH    0
#define SM_AL    16384
#define SM_BB    32768
#define SM_BUF   49152
#define SM_TOK   98304
#define SM_COEF  98816
#define SM_TILE  99328
#define SM_TOTAL 99344

__device__ __forceinline__ uint32_t smem_u32(const void* p) {
    uint32_t a;
    asm("{ .reg .u64 t; cvta.to.shared.u64 t, %1; cvt.u32.u64 %0, t; }" : "=r"(a) : "l"(p));
    return a;
}
#define LDSM_X4(r, addr) \
    asm volatile("ldmatrix.sync.aligned.m8n8.x4.shared.b16 {%0,%1,%2,%3}, [%4];" \
        : "=r"((r)[0]), "=r"((r)[1]), "=r"((r)[2]), "=r"((r)[3]) : "r"(addr))
#define MMAF16(c, a, b0, b1) \
    asm volatile("mma.sync.aligned.m16n8k16.row.col.f32.f16.f16.f32 " \
        "{%0,%1,%2,%3}, {%4,%5,%6,%7}, {%8,%9}, {%0,%1,%2,%3};" \
        : "+f"((c)[0]), "+f"((c)[1]), "+f"((c)[2]), "+f"((c)[3]) \
        : "r"((a)[0]), "r"((a)[1]), "r"((a)[2]), "r"((a)[3]), "r"(b0), "r"(b1))
#define CP16(dst, src) \
    asm volatile("cp.async.cg.shared.global [%0], [%1], 16;" :: "r"(dst), "l"(src))
#define CP_COMMIT() asm volatile("cp.async.commit_group;" ::: "memory")
#define CP_WAIT0()  asm volatile("cp.async.wait_group 0;" ::: "memory")

// fp4 pair -> packed fp16x2 (exact); adjc = 0x3800 + (s-127)<<10
__device__ __forceinline__ uint32_t dq16(uint32_t byte, uint32_t adjc) {
    uint32_t n0 = byte & 15u, n1 = (byte >> 4) & 15u;
    uint32_t m0 = n0 & 7u, m1 = n1 & 7u;
    uint32_t b0 = (m0 == 0u) ? 0u : (adjc + ((m0 >= 2u) ? (m0 << 9) : 0u));
    uint32_t b1 = (m1 == 0u) ? 0u : (adjc + ((m1 >= 2u) ? (m1 << 9) : 0u));
    b0 |= (n0 & 8u) << 12;  b1 |= (n1 & 8u) << 12;
    return b0 | (b1 << 16);
}

__device__ int   g_top_idx[NTOK][2];
__device__ float g_top_w[NTOK][2];
__device__ int   g_count[NE];
__device__ int   g_off[NE];
__device__ int   g_list[NE][NTOK];
__device__ float g_coefs[NE][NTOK];
__device__ unsigned short g_x_h[(size_t)NTOK * D_HIDDEN];
__device__ unsigned short g_x_l[(size_t)NTOK * D_HIDDEN];
__device__ unsigned short g_act[(size_t)NPAIR * D_INTER];
__device__ uint4 g_gu_pack[(size_t)NE * GU_ROWS * 32];
__device__ uint4 g_dn_pack[(size_t)NE * D_HIDDEN * 128];
__device__ int g_mt[128];     // live m-tiles: e | (m0idx << 4)
__device__ int g_nmt;
__device__ int g_ctr1, g_ctr2;

__global__ void zero_kernel(float* __restrict__ out, int n) {
    int i = blockIdx.x * blockDim.x + threadIdx.x;
    if (i < n) out[i] = 0.0f;
}
__global__ void prep_x_kernel(const float* __restrict__ x) {
    int row = blockIdx.x;
    int c = threadIdx.x * 4;
    float4 f = *(const float4*)(x + (size_t)row * D_HIDDEN + c);
    float v[4] = {f.x, f.y, f.z, f.w};
    unsigned short h[4], l[4];
#pragma unroll
    for (int i = 0; i < 4; i++) {
        __half hh = __float2half_rn(v[i]);
        h[i] = __half_as_ushort(hh);
        l[i] = __half_as_ushort(__float2half_rn(v[i] - __half2float(hh)));
    }
    uint2 ph, pl;
    ph.x = (uint32_t)h[0] | ((uint32_t)h[1] << 16); ph.y = (uint32_t)h[2] | ((uint32_t)h[3] << 16);
    pl.x = (uint32_t)l[0] | ((uint32_t)l[1] << 16); pl.y = (uint32_t)l[2] | ((uint32_t)l[3] << 16);
    *(uint2*)(g_x_h + (size_t)row * D_HIDDEN + c) = ph;
    *(uint2*)(g_x_l + (size_t)row * D_HIDDEN + c) = pl;
}
__global__ void pack_kernel(const int* __restrict__ src, uint4* __restrict__ dst) {
    size_t i = (size_t)blockIdx.x * 256 + threadIdx.x;
    const int4* s = (const int4*)src + i * 4;
    int4 a = s[0], b = s[1], c = s[2], d = s[3];
    uint4 o;
    o.x = (a.x & 255) | ((a.y & 255) << 8) | ((a.z & 255) << 16) | ((a.w & 255) << 24);
    o.y = (b.x & 255) | ((b.y & 255) << 8) | ((b.z & 255) << 16) | ((b.w & 255) << 24);
    o.z = (c.x & 255) | ((c.y & 255) << 8) | ((c.z & 255) << 16) | ((c.w & 255) << 24);
    o.w = (d.x & 255) | ((d.y & 255) << 8) | ((d.z & 255) << 16) | ((d.w & 255) << 24);
    dst[i] = o;
}
__global__ void router_kernel(const float* __restrict__ x,
                              const float* __restrict__ rw,
                              const float* __restrict__ rb) {
    int warp = threadIdx.x >> 5, lane = threadIdx.x & 31;
    int t = blockIdx.x * 8 + warp;
    if (t >= NTOK) return;
    float acc[NE];
#pragma unroll
    for (int e = 0; e < NE; e++) acc[e] = 0.0f;
    const float* xr = x + (size_t)t * D_HIDDEN;
    for (int k = lane; k < D_HIDDEN; k += 32) {
        float xv = xr[k];
#pragma unroll
        for (int e = 0; e < NE; e++) acc[e] += xv * rw[e * D_HIDDEN + k];
    }
#pragma unroll
    for (int e = 0; e < NE; e++)
#pragma unroll
        for (int o = 16; o > 0; o >>= 1) acc[e] += __shfl_xor_sync(0xffffffffu, acc[e], o);
    if (lane == 0) {
        float v[NE];
#pragma unroll
        for (int e = 0; e < NE; e++) v[e] = acc[e] + rb[e];
        int i0 = 0;
#pragma unroll
        for (int e = 1; e < NE; e++) if (v[e] > v[i0]) i0 = e;
        int i1 = -1;
#pragma unroll
        for (int e = 0; e < NE; e++) {
            if (e == i0) continue;
            if (i1 < 0 || v[e] > v[i1]) i1 = e;
        }
        float w1 = expf(v[i1] - v[i0]);
        float inv = 1.0f / (1.0f + w1);
        g_top_idx[t][0] = i0; g_top_idx[t][1] = i1;
        g_top_w[t][0] = inv;  g_top_w[t][1] = w1 * inv;
    }
}
__global__ void compact_kernel() {
    const int e = blockIdx.x, tid = threadIdx.x;
    __shared__ int scan[256];
    __shared__ int sbase;
    if (tid == 0) sbase = 0;
    __syncthreads();
    for (int c = 0; c < NTOK; c += 256) {
        int t = c + tid;
        int flag = (g_top_idx[t][0] == e) || (g_top_idx[t][1] == e);
        float coef = (g_top_idx[t][0] == e) ? g_top_w[t][0] : g_top_w[t][1];
        scan[tid] = flag;
        __syncthreads();
#pragma unroll
        for (int off = 1; off < 256; off <<= 1) {
            int v = (tid >= off) ? scan[tid - off] : 0;
            __syncthreads();
            scan[tid] += v;
            __syncthreads();
        }
        if (flag) {
            int pos = sbase + scan[tid] - 1;
            g_list[e][pos] = t; g_coefs[e][pos] = coef;
        }
        __syncthreads();
        if (tid == 0) sbase += scan[255];
        __syncthreads();
    }
    if (tid == 0) g_count[e] = sbase;
}
// offsets + live-tile list + counter reset (single thread; trivial work)
__global__ void offsets_kernel() {
    if (threadIdx.x == 0) {
        int r = 0, n = 0;
#pragma unroll
        for (int e = 0; e < NE; e++) {
            g_off[e] = r;
            int cnt = g_count[e];
            r += cnt;
            int mt = (cnt + 127) >> 7;
            for (int m = 0; m < mt; m++) g_mt[n++] = e | (m << 4);
        }
        g_nmt = n;
        g_ctr1 = 0;
        g_ctr2 = 0;
    }
}

// ============================================================
// GEMM1 (persistent): fp16 hi+lo planes, 128x128 tile, BK=64,
// 8 warps (4M x 2N), warp 32x64, double-buffered cp.async.
// ============================================================
__global__ __launch_bounds__(256, 2) void gemm1_kernel(
    const int* __restrict__ gus, const float* __restrict__ gbias) {
    extern __shared__ char smem[];
    const uint32_t sb = smem_u32(smem);
    const int tid = threadIdx.x, wid = tid >> 5, lane = tid & 31;
    const int wm = wid & 3, wn = wid >> 2;
    int* stok = (int*)(smem + SM_TOK);
    int* stile = (int*)(smem + SM_TILE);

    // tile-invariant ldmatrix address precompute
    uint32_t aAddr[2], arx[2];
#pragma unroll
    for (int mf = 0; mf < 2; mf++) {
        int r = wm * 32 + mf * 16 + (lane & 15);
        aAddr[mf] = sb + ((uint32_t)r << 7);
        arx[mf] = ((uint32_t)r & 7u) << 4;
    }
    const uint32_t a_cb = (uint32_t)(lane >> 4) << 4;
    uint32_t bAddr[4], brxv[4];
#pragma unroll
    for (int g = 0; g < 4; g++) {
        int r = wn * 64 + g * 16 + ((lane >> 4) << 3) + (lane & 7);
        bAddr[g] = sb + SM_BB + ((uint32_t)r << 7);
        brxv[g] = ((uint32_t)r & 7u) << 4;
    }
    const uint32_t b_cb = ((uint32_t)(lane >> 3) & 1u) << 4;
    const int arow = tid >> 1, kh = (tid & 1) << 5;
    const uint32_t fbase = (uint32_t)arow << 7;
    const uint32_t frx = ((uint32_t)arow & 7u) << 4;
    uint32_t fo[4];
#pragma unroll
    for (int j = 0; j < 4; j++)
        fo[j] = fbase + ((((uint32_t)(kh + j * 8)) << 1) ^ frx);

    for (;;) {
        if (tid == 0) stile[0] = atomicAdd(&g_ctr1, 1);
        __syncthreads();
        const int t = stile[0];
        if (t >= g_nmt * 64) break;
        const int mv = g_mt[t >> 6];
        const int e = mv & 15;
        const int m0 = (mv >> 4) << 7;
        const int r0 = (t & 63) << 7;
        const int cnt = g_count[e];
        const int valid = min(128, cnt - m0);
        const int off = g_off[e];

        if (tid < 128) stok[tid] = g_list[e][m0 + (tid < valid ? tid : 0)];
        __syncthreads();

        const unsigned short* xh = g_x_h + (size_t)stok[arow] * D_HIDDEN + kh;
        const unsigned short* xl = g_x_l + (size_t)stok[arow] * D_HIDDEN + kh;
        const uint4* bw = g_gu_pack + (size_t)(e * GU_ROWS + r0 + arow) * 32;
        const int*  sc = gus + (size_t)(e * GU_ROWS + r0 + arow) * 32;

        float acc[2][8][4];
#pragma unroll
        for (int mf = 0; mf < 2; mf++)
#pragma unroll
            for (int nf = 0; nf < 8; nf++)
#pragma unroll
                for (int j = 0; j < 4; j++) acc[mf][nf][j] = 0.0f;

#pragma unroll
        for (int j = 0; j < 4; j++) {
            CP16(sb + SM_AH + fo[j], xh + j * 8);
            CP16(sb + SM_AL + fo[j], xl + j * 8);
        }
        CP_COMMIT();
        uint4 ub = bw[tid & 1];
        uint32_t adj = 0x3800u + (uint32_t)((sc[tid & 1] - 127) << 10);

        const int NKB = D_HIDDEN / 64;
        for (int kb = 0; kb < NKB; kb++) {
            const uint32_t bo = (uint32_t)(kb & 1) * SM_BUF;
            {
                uint32_t w4[4] = {ub.x, ub.y, ub.z, ub.w};
#pragma unroll
                for (int q = 0; q < 4; q++) {
                    uint32_t ww = w4[q];
                    uint4 r;
                    r.x = dq16(ww & 255u, adj);
                    r.y = dq16((ww >> 8) & 255u, adj);
                    r.z = dq16((ww >> 16) & 255u, adj);
                    r.w = dq16(ww >> 24, adj);
                    *(uint4*)(smem + bo + SM_BB + fo[q]) = r;
                }
            }
            CP_WAIT0();
            __syncthreads();
            if (kb + 1 < NKB) {
                const uint32_t bo2 = (uint32_t)((kb + 1) & 1) * SM_BUF;
#pragma unroll
                for (int j = 0; j < 4; j++) {
                    CP16(sb + bo2 + SM_AH + fo[j], xh + (kb + 1) * 64 + j * 8);
                    CP16(sb + bo2 + SM_AL + fo[j], xl + (kb + 1) * 64 + j * 8);
                }
                CP_COMMIT();
                int bin = (kb + 1) * 2 + (tid & 1);
                ub = bw[bin];
                adj = 0x3800u + (uint32_t)((sc[bin] - 127) << 10);
            }
#pragma unroll
            for (int ks = 0; ks < 4; ks++) {
                uint32_t acol = (uint32_t)ks * 32 + a_cb;
                uint32_t bcol = (uint32_t)ks * 32 + b_cb;
                uint32_t Ah[2][4], Al[2][4], Bf[4][4];
#pragma unroll
                for (int mf = 0; mf < 2; mf++) {
                    LDSM_X4(Ah[mf], aAddr[mf] + bo + SM_AH + (acol ^ arx[mf]));
                    LDSM_X4(Al[mf], aAddr[mf] + bo + SM_AL + (acol ^ arx[mf]));
                }
#pragma unroll
                for (int g = 0; g < 4; g++) LDSM_X4(Bf[g], bAddr[g] + bo + (bcol ^ brxv[g]));
#pragma unroll
                for (int mf = 0; mf < 2; mf++)
#pragma unroll
                    for (int nf = 0; nf < 8; nf++) {
                        uint32_t bb0 = Bf[nf >> 1][(nf & 1) * 2];
                        uint32_t bb1 = Bf[nf >> 1][(nf & 1) * 2 + 1];
                        MMAF16(acc[mf][nf], Ah[mf], bb0, bb1);
                        MMAF16(acc[mf][nf], Al[mf], bb0, bb1);
                    }
            }
        }
        __syncthreads();

        // epilogue: bias + SwiGLU -> stage -> single fp16 act plane
        const float* gb = gbias + (size_t)e * GU_ROWS;
        unsigned short* stage = (unsigned short*)smem;
#pragma unroll
        for (int mf = 0; mf < 2; mf++)
#pragma unroll
            for (int nf = 0; nf < 8; nf++) {
                int gucol = r0 + wn * 64 + nf * 8 + (lane & 3) * 2;
                float bg = gb[gucol], bu = gb[gucol + 1];
                int cl = wn * 32 + nf * 4 + (lane & 3);
#pragma unroll
                for (int rr = 0; rr < 2; rr++) {
                    int r = wm * 32 + mf * 16 + (lane >> 2) + rr * 8;
                    float gate = acc[mf][nf][rr * 2 + 0] + bg;
                    float up   = acc[mf][nf][rr * 2 + 1] + bu;
                    gate = fminf(gate, 7.0f);
                    up = fminf(fmaxf(up, -7.0f), 7.0f);
                    float sg = 1.0f / (1.0f + __expf(-1.702f * gate));
                    float a = (up + 1.0f) * (gate * sg);
                    stage[r * 72 + cl] = __half_as_ushort(__float2half_rn(a));
                }
            }
        __syncthreads();
        {
            int row = tid >> 1;
            if (row < valid) {
                size_t gbase = (size_t)(off + m0 + row) * D_INTER + (r0 >> 1) + (tid & 1) * 32;
                uint4* dh = (uint4*)(g_act + gbase);
                const uint4* shp = (const uint4*)(stage + row * 72 + (tid & 1) * 32);
#pragma unroll
                for (int i = 0; i < 4; i++) dh[i] = shp[i];
            }
        }
        __syncthreads();
    }
}

// ============================================================
// GEMM2 (persistent, single fp16 plane)
// ============================================================
__global__ __launch_bounds__(256, 2) void gemm2_kernel(
    const int* __restrict__ dns, const float* __restrict__ dbias,
    float* __restrict__ out) {
    extern __shared__ char smem[];
    const uint32_t sb = smem_u32(smem);
    const int tid = threadIdx.x, wid = tid >> 5, lane = tid & 31;
    const int wm = wid & 3, wn = wid >> 2;
    int* stok = (int*)(smem + SM_TOK);
    float* scoef = (float*)(smem + SM_COEF);
    int* stile = (int*)(smem + SM_TILE);

    uint32_t aAddr[2], arx[2];
#pragma unroll
    for (int mf = 0; mf < 2; mf++) {
        int r = wm * 32 + mf * 16 + (lane & 15);
        aAddr[mf] = sb + ((uint32_t)r << 7);
        arx[mf] = ((uint32_t)r & 7u) << 4;
    }
    const uint32_t a_cb = (uint32_t)(lane >> 4) << 4;
    uint32_t bAddr[4], brxv[4];
#pragma unroll
    for (int g = 0; g < 4; g++) {
        int r = wn * 64 + g * 16 + ((lane >> 4) << 3) + (lane & 7);
        bAddr[g] = sb + SM_BB + ((uint32_t)r << 7);
        brxv[g] = ((uint32_t)r & 7u) << 4;
    }
    const uint32_t b_cb = ((uint32_t)(lane >> 3) & 1u) << 4;
    const int arow = tid >> 1, kh = (tid & 1) << 5;
    const uint32_t fbase = (uint32_t)arow << 7;
    const uint32_t frx = ((uint32_t)arow & 7u) << 4;
    uint32_t fo[4];
#pragma unroll
    for (int j = 0; j < 4; j++)
        fo[j] = fbase + ((((uint32_t)(kh + j * 8)) << 1) ^ frx);

    for (;;) {
        if (tid == 0) stile[0] = atomicAdd(&g_ctr2, 1);
        __syncthreads();
        const int t = stile[0];
        if (t >= g_nmt * 8) break;
        const int mv = g_mt[t >> 3];
        const int e = mv & 15;
        const int m0 = (mv >> 4) << 7;
        const int r0 = (t & 7) << 7;
        const int cnt = g_count[e];
        const int valid = min(128, cnt - m0);
        const int off = g_off[e];

        if (tid < 128) {
            int mm = (tid < valid) ? tid : 0;
            stok[tid] = g_list[e][m0 + mm];
            scoef[tid] = g_coefs[e][m0 + mm];
        }
        __syncthreads();

        const int pr = off + m0 + ((arow < valid) ? arow : 0);
        const unsigned short* ah = g_act + (size_t)pr * D_INTER + kh;
        const uint4* bw = g_dn_pack + (size_t)(e * D_HIDDEN + r0 + arow) * 128;
        const int*  sc = dns + (size_t)(e * D_HIDDEN + r0 + arow) * 128;

        float acc[2][8][4];
#pragma unroll
        for (int mf = 0; mf < 2; mf++)
#pragma unroll
            for (int nf = 0; nf < 8; nf++)
#pragma unroll
                for (int j = 0; j < 4; j++) acc[mf][nf][j] = 0.0f;

#pragma unroll
        for (int j = 0; j < 4; j++) CP16(sb + SM_AH + fo[j], ah + j * 8);
        CP_COMMIT();
        uint4 ub = bw[tid & 1];
        uint32_t adj = 0x3800u + (uint32_t)((sc[tid & 1] - 127) << 10);

        const int NKB = D_INTER / 64;
        for (int kb = 0; kb < NKB; kb++) {
            const uint32_t bo = (uint32_t)(kb & 1) * SM_BUF;
            {
                uint32_t w4[4] = {ub.x, ub.y, ub.z, ub.w};
#pragma unroll
                for (int q = 0; q < 4; q++) {
                    uint32_t ww = w4[q];
                    uint4 r;
                    r.x = dq16(ww & 255u, adj);
                    r.y = dq16((ww >> 8) & 255u, adj);
                    r.z = dq16((ww >> 16) & 255u, adj);
                    r.w = dq16(ww >> 24, adj);
                    *(uint4*)(smem + bo + SM_BB + fo[q]) = r;
                }
            }
            CP_WAIT0();
            __syncthreads();
            if (kb + 1 < NKB) {
                const uint32_t bo2 = (uint32_t)((kb + 1) & 1) * SM_BUF;
#pragma unroll
                for (int j = 0; j < 4; j++)
                    CP16(sb + bo2 + SM_AH + fo[j], ah + (kb + 1) * 64 + j * 8);
                CP_COMMIT();
                int bin = (kb + 1) * 2 + (tid & 1);
                ub = bw[bin];
                adj = 0x3800u + (uint32_t)((sc[bin] - 127) << 10);
            }
#pragma unroll
            for (int ks = 0; ks < 4; ks++) {
                uint32_t acol = (uint32_t)ks * 32 + a_cb;
                uint32_t bcol = (uint32_t)ks * 32 + b_cb;
                uint32_t Ah[2][4], Bf[4][4];
#pragma unroll
                for (int mf = 0; mf < 2; mf++)
                    LDSM_X4(Ah[mf], aAddr[mf] + bo + SM_AH + (acol ^ arx[mf]));
#pragma unroll
                for (int g = 0; g < 4; g++) LDSM_X4(Bf[g], bAddr[g] + bo + (bcol ^ brxv[g]));
#pragma unroll
                for (int mf = 0; mf < 2; mf++)
#pragma unroll
                    for (int nf = 0; nf < 8; nf++) {
                        uint32_t bb0 = Bf[nf >> 1][(nf & 1) * 2];
                        uint32_t bb1 = Bf[nf >> 1][(nf & 1) * 2 + 1];
                        MMAF16(acc[mf][nf], Ah[mf], bb0, bb1);
                    }
            }
        }

        const float* db = dbias + (size_t)e * D_HIDDEN;
#pragma unroll
        for (int mf = 0; mf < 2; mf++)
#pragma unroll
            for (int nf = 0; nf < 8; nf++) {
                int gcol = r0 + wn * 64 + nf * 8 + (lane & 3) * 2;
                float b0 = db[gcol], b1 = db[gcol + 1];
#pragma unroll
                for (int rr = 0; rr < 2; rr++) {
                    int m = wm * 32 + mf * 16 + (lane >> 2) + rr * 8;
                    if (m < valid) {
                        float coef = scoef[m];
                        float* orow = out + (size_t)stok[m] * D_HIDDEN;
                        atomicAdd(orow + gcol,     coef * (acc[mf][nf][rr * 2 + 0] + b0));
                        atomicAdd(orow + gcol + 1, coef * (acc[mf][nf][rr * 2 + 1] + b1));
                    }
                }
            }
        __syncthreads();
    }
}

// ============================================================
extern "C" void kernel_launch(void* const* d_in, const int* in_sizes, int n_in,
                              void* d_out, int out_size) {
    const float* x     = (const float*)d_in[0];
    const float* rw    = (const float*)d_in[1];
    const float* rb    = (const float*)d_in[2];
    const float* gbias = (const float*)d_in[3];
    const float* dbias = (const float*)d_in[4];
    const int*   gub   = (const int*)d_in[5];
    const int*   gus   = (const int*)d_in[6];
    const int*   dnb   = (const int*)d_in[7];
    const int*   dns   = (const int*)d_in[8];
    float* out = (float*)d_out;

    cudaFuncSetAttribute(gemm1_kernel, cudaFuncAttributeMaxDynamicSharedMemorySize, SM_TOTAL);
    cudaFuncSetAttribute(gemm2_kernel, cudaFuncAttributeMaxDynamicSharedMemorySize, SM_TOTAL);
    uint4* gu_pack; cudaGetSymbolAddress((void**)&gu_pack, g_gu_pack);
    uint4* dn_pack; cudaGetSymbolAddress((void**)&dn_pack, g_dn_pack);

    zero_kernel<<<(out_size + 255) / 256, 256>>>(out, out_size);
    prep_x_kernel<<<NTOK, 256>>>(x);
    pack_kernel<<<8192, 256>>>(gub, gu_pack);
    pack_kernel<<<4096, 256>>>(dnb, dn_pack);
    router_kernel<<<NTOK / 8, 256>>>(x, rw, rb);
    compact_kernel<<<NE, 256>>>();
    offsets_kernel<<<1, 32>>>();
    gemm1_kernel<<<296, 256, SM_TOTAL>>>(gus, gbias);
    gemm2_kernel<<<296, 256, SM_TOTAL>>>(dns, dbias, out);
}

// round 15
// speedup vs baseline: 1.5492x; 1.1448x over previous
#include <cuda_runtime.h>
#include <cuda_fp16.h>
#include <math.h>
#include <stdint.h>

#define D_HIDDEN 1024
#define D_INTER  4096
#define NE       8
#define NTOK     2048
#define NPAIR    (NTOK * 2)
#define GU_ROWS  8192

// per-buffer: AH 16K | AL 16K | B 16K ; two buffers (stride 48K)
#define SM_AH    0
#define SM_AL    16384
#define SM_BB    32768
#define SM_BUF   49152
#define SM_TOK   98304
#define SM_COEF  98816
#define SM_TOTAL 99328

__device__ __forceinline__ uint32_t smem_u32(const void* p) {
    uint32_t a;
    asm("{ .reg .u64 t; cvta.to.shared.u64 t, %1; cvt.u32.u64 %0, t; }" : "=r"(a) : "l"(p));
    return a;
}
#define LDSM_X4(r, addr) \
    asm volatile("ldmatrix.sync.aligned.m8n8.x4.shared.b16 {%0,%1,%2,%3}, [%4];" \
        : "=r"((r)[0]), "=r"((r)[1]), "=r"((r)[2]), "=r"((r)[3]) : "r"(addr))
#define MMAF16(c, a, b0, b1) \
    asm volatile("mma.sync.aligned.m16n8k16.row.col.f32.f16.f16.f32 " \
        "{%0,%1,%2,%3}, {%4,%5,%6,%7}, {%8,%9}, {%0,%1,%2,%3};" \
        : "+f"((c)[0]), "+f"((c)[1]), "+f"((c)[2]), "+f"((c)[3]) \
        : "r"((a)[0]), "r"((a)[1]), "r"((a)[2]), "r"((a)[3]), "r"(b0), "r"(b1))
#define CP16(dst, src) \
    asm volatile("cp.async.cg.shared.global [%0], [%1], 16;" :: "r"(dst), "l"(src))
#define CP_COMMIT() asm volatile("cp.async.commit_group;" ::: "memory")
#define CP_WAIT0()  asm volatile("cp.async.wait_group 0;" ::: "memory")

// fp4 pair -> packed fp16x2 (exact); adjc = 0x3800 + (s-127)<<10
__device__ __forceinline__ uint32_t dq16(uint32_t byte, uint32_t adjc) {
    uint32_t n0 = byte & 15u, n1 = (byte >> 4) & 15u;
    uint32_t m0 = n0 & 7u, m1 = n1 & 7u;
    uint32_t b0 = (m0 == 0u) ? 0u : (adjc + ((m0 >= 2u) ? (m0 << 9) : 0u));
    uint32_t b1 = (m1 == 0u) ? 0u : (adjc + ((m1 >= 2u) ? (m1 << 9) : 0u));
    b0 |= (n0 & 8u) << 12;  b1 |= (n1 & 8u) << 12;
    return b0 | (b1 << 16);
}

__device__ int   g_top_idx[NTOK][2];
__device__ float g_top_w[NTOK][2];
__device__ int   g_count[NE];
__device__ int   g_off[NE];
__device__ int   g_list[NE][NTOK];
__device__ float g_coefs[NE][NTOK];
__device__ unsigned short g_x_h[(size_t)NTOK * D_HIDDEN];
__device__ unsigned short g_x_l[(size_t)NTOK * D_HIDDEN];
__device__ unsigned short g_act[(size_t)NPAIR * D_INTER];
__device__ unsigned short g_gu16[(size_t)NE * GU_ROWS * D_HIDDEN];   // 134 MB fp16 weights
__device__ unsigned short g_dn16[(size_t)NE * D_HIDDEN * D_INTER];   // 67 MB

__global__ void zero_kernel(float* __restrict__ out, int n) {
    int i = blockIdx.x * blockDim.x + threadIdx.x;
    if (i < n) out[i] = 0.0f;
}
__global__ void prep_x_kernel(const float* __restrict__ x) {
    int row = blockIdx.x;
    int c = threadIdx.x * 4;
    float4 f = *(const float4*)(x + (size_t)row * D_HIDDEN + c);
    float v[4] = {f.x, f.y, f.z, f.w};
    unsigned short h[4], l[4];
#pragma unroll
    for (int i = 0; i < 4; i++) {
        __half hh = __float2half_rn(v[i]);
        h[i] = __half_as_ushort(hh);
        l[i] = __half_as_ushort(__float2half_rn(v[i] - __half2float(hh)));
    }
    uint2 ph, pl;
    ph.x = (uint32_t)h[0] | ((uint32_t)h[1] << 16); ph.y = (uint32_t)h[2] | ((uint32_t)h[3] << 16);
    pl.x = (uint32_t)l[0] | ((uint32_t)l[1] << 16); pl.y = (uint32_t)l[2] | ((uint32_t)l[3] << 16);
    *(uint2*)(g_x_h + (size_t)row * D_HIDDEN + c) = ph;
    *(uint2*)(g_x_l + (size_t)row * D_HIDDEN + c) = pl;
}
// inflated int32 fp4-bytes + scales -> fp16 weights (8 elems/thread)
// bpr_b: bytes per row; spr: scale blocks per row
__global__ void prequant_kernel(const int* __restrict__ src, const int* __restrict__ scales,
                                unsigned short* __restrict__ dst, int bpr_b, int spr) {
    size_t g = (size_t)blockIdx.x * 256 + threadIdx.x;   // 4 bytes -> 8 elems
    size_t row = (g * 4) / (size_t)bpr_b;
    int bcol = (int)((g * 4) % (size_t)bpr_b);
    const int4 q = *(const int4*)(src + row * bpr_b + bcol);
    int s = scales[row * spr + (bcol >> 4)];
    uint32_t adj = 0x3800u + (uint32_t)((s - 127) << 10);
    uint4 o;
    o.x = dq16((uint32_t)q.x & 255u, adj);
    o.y = dq16((uint32_t)q.y & 255u, adj);
    o.z = dq16((uint32_t)q.z & 255u, adj);
    o.w = dq16((uint32_t)q.w & 255u, adj);
    *(uint4*)(dst + g * 8) = o;
}
__global__ void router_kernel(const float* __restrict__ x,
                              const float* __restrict__ rw,
                              const float* __restrict__ rb) {
    int warp = threadIdx.x >> 5, lane = threadIdx.x & 31;
    int t = blockIdx.x * 8 + warp;
    if (t >= NTOK) return;
    float acc[NE];
#pragma unroll
    for (int e = 0; e < NE; e++) acc[e] = 0.0f;
    const float* xr = x + (size_t)t * D_HIDDEN;
    for (int k = lane; k < D_HIDDEN; k += 32) {
        float xv = xr[k];
#pragma unroll
        for (int e = 0; e < NE; e++) acc[e] += xv * rw[e * D_HIDDEN + k];
    }
#pragma unroll
    for (int e = 0; e < NE; e++)
#pragma unroll
        for (int o = 16; o > 0; o >>= 1) acc[e] += __shfl_xor_sync(0xffffffffu, acc[e], o);
    if (lane == 0) {
        float v[NE];
#pragma unroll
        for (int e = 0; e < NE; e++) v[e] = acc[e] + rb[e];
        int i0 = 0;
#pragma unroll
        for (int e = 1; e < NE; e++) if (v[e] > v[i0]) i0 = e;
        int i1 = -1;
#pragma unroll
        for (int e = 0; e < NE; e++) {
            if (e == i0) continue;
            if (i1 < 0 || v[e] > v[i1]) i1 = e;
        }
        float w1 = expf(v[i1] - v[i0]);
        float inv = 1.0f / (1.0f + w1);
        g_top_idx[t][0] = i0; g_top_idx[t][1] = i1;
        g_top_w[t][0] = inv;  g_top_w[t][1] = w1 * inv;
    }
}
__global__ void compact_kernel() {
    const int e = blockIdx.x, tid = threadIdx.x;
    __shared__ int scan[256];
    __shared__ int sbase;
    if (tid == 0) sbase = 0;
    __syncthreads();
    for (int c = 0; c < NTOK; c += 256) {
        int t = c + tid;
        int flag = (g_top_idx[t][0] == e) || (g_top_idx[t][1] == e);
        float coef = (g_top_idx[t][0] == e) ? g_top_w[t][0] : g_top_w[t][1];
        scan[tid] = flag;
        __syncthreads();
#pragma unroll
        for (int off = 1; off < 256; off <<= 1) {
            int v = (tid >= off) ? scan[tid - off] : 0;
            __syncthreads();
            scan[tid] += v;
            __syncthreads();
        }
        if (flag) {
            int pos = sbase + scan[tid] - 1;
            g_list[e][pos] = t; g_coefs[e][pos] = coef;
        }
        __syncthreads();
        if (tid == 0) sbase += scan[255];
        __syncthreads();
    }
    if (tid == 0) g_count[e] = sbase;
}
__global__ void offsets_kernel() {
    if (threadIdx.x == 0) {
        int r = 0;
#pragma unroll
        for (int e = 0; e < NE; e++) { g_off[e] = r; r += g_count[e]; }
    }
}

// ============================================================
// GEMM1: fp16 hi+lo planes, B via cp.async from prequantized fp16.
// 128x128 tile, BK=64, 8 warps (4M x 2N), warp 32x64, double-buffered.
// ============================================================
__global__ __launch_bounds__(256, 2) void gemm1_kernel(const float* __restrict__ gbias) {
    const int e  = blockIdx.y >> 6;
    const int r0 = (blockIdx.y & 63) << 7;
    const int m0 = blockIdx.x << 7;
    const int cnt = g_count[e];
    if (m0 >= cnt) return;
    const int valid = min(128, cnt - m0);
    const int off = g_off[e];
    extern __shared__ char smem[];
    const uint32_t sb = smem_u32(smem);
    const int tid = threadIdx.x, wid = tid >> 5, lane = tid & 31;
    const int wm = wid & 3, wn = wid >> 2;

    int* stok = (int*)(smem + SM_TOK);
    if (tid < 128) stok[tid] = g_list[e][m0 + (tid < valid ? tid : 0)];
    __syncthreads();

    const int arow = tid >> 1, kh = (tid & 1) << 5;
    const unsigned short* xh = g_x_h + (size_t)stok[arow] * D_HIDDEN + kh;
    const unsigned short* xl = g_x_l + (size_t)stok[arow] * D_HIDDEN + kh;
    const unsigned short* bwp = g_gu16 + (size_t)(e * GU_ROWS + r0 + arow) * D_HIDDEN + kh;
    const uint32_t fbase = (uint32_t)arow << 7;
    const uint32_t frx = ((uint32_t)arow & 7u) << 4;
    uint32_t fo[4];
#pragma unroll
    for (int j = 0; j < 4; j++)
        fo[j] = fbase + ((((uint32_t)(kh + j * 8)) << 1) ^ frx);

    uint32_t aAddr[2], arx[2];
#pragma unroll
    for (int mf = 0; mf < 2; mf++) {
        int r = wm * 32 + mf * 16 + (lane & 15);
        aAddr[mf] = sb + ((uint32_t)r << 7);
        arx[mf] = ((uint32_t)r & 7u) << 4;
    }
    const uint32_t a_cb = (uint32_t)(lane >> 4) << 4;
    uint32_t bAddr[4], brxv[4];
#pragma unroll
    for (int g = 0; g < 4; g++) {
        int r = wn * 64 + g * 16 + ((lane >> 4) << 3) + (lane & 7);
        bAddr[g] = sb + SM_BB + ((uint32_t)r << 7);
        brxv[g] = ((uint32_t)r & 7u) << 4;
    }
    const uint32_t b_cb = ((uint32_t)(lane >> 3) & 1u) << 4;

    float acc[2][8][4];
#pragma unroll
    for (int mf = 0; mf < 2; mf++)
#pragma unroll
        for (int nf = 0; nf < 8; nf++)
#pragma unroll
            for (int j = 0; j < 4; j++) acc[mf][nf][j] = 0.0f;

#pragma unroll
    for (int j = 0; j < 4; j++) {
        CP16(sb + SM_AH + fo[j], xh + j * 8);
        CP16(sb + SM_AL + fo[j], xl + j * 8);
        CP16(sb + SM_BB + fo[j], bwp + j * 8);
    }
    CP_COMMIT();

    const int NKB = D_HIDDEN / 64;
    for (int kb = 0; kb < NKB; kb++) {
        const uint32_t bo = (uint32_t)(kb & 1) * SM_BUF;
        CP_WAIT0();
        __syncthreads();
        if (kb + 1 < NKB) {
            const uint32_t bo2 = (uint32_t)((kb + 1) & 1) * SM_BUF;
#pragma unroll
            for (int j = 0; j < 4; j++) {
                CP16(sb + bo2 + SM_AH + fo[j], xh + (kb + 1) * 64 + j * 8);
                CP16(sb + bo2 + SM_AL + fo[j], xl + (kb + 1) * 64 + j * 8);
                CP16(sb + bo2 + SM_BB + fo[j], bwp + (kb + 1) * 64 + j * 8);
            }
            CP_COMMIT();
        }
#pragma unroll
        for (int ks = 0; ks < 4; ks++) {
            uint32_t acol = (uint32_t)ks * 32 + a_cb;
            uint32_t bcol = (uint32_t)ks * 32 + b_cb;
            uint32_t Ah[2][4], Al[2][4], Bf[4][4];
#pragma unroll
            for (int mf = 0; mf < 2; mf++) {
                LDSM_X4(Ah[mf], aAddr[mf] + bo + SM_AH + (acol ^ arx[mf]));
                LDSM_X4(Al[mf], aAddr[mf] + bo + SM_AL + (acol ^ arx[mf]));
            }
#pragma unroll
            for (int g = 0; g < 4; g++) LDSM_X4(Bf[g], bAddr[g] + bo + (bcol ^ brxv[g]));
#pragma unroll
            for (int mf = 0; mf < 2; mf++)
#pragma unroll
                for (int nf = 0; nf < 8; nf++) {
                    uint32_t bb0 = Bf[nf >> 1][(nf & 1) * 2];
                    uint32_t bb1 = Bf[nf >> 1][(nf & 1) * 2 + 1];
                    MMAF16(acc[mf][nf], Ah[mf], bb0, bb1);
                    MMAF16(acc[mf][nf], Al[mf], bb0, bb1);
                }
        }
    }
    __syncthreads();

    // epilogue: bias + SwiGLU -> stage -> single fp16 act plane
    const float* gb = gbias + (size_t)e * GU_ROWS;
    unsigned short* stage = (unsigned short*)smem;
#pragma unroll
    for (int mf = 0; mf < 2; mf++)
#pragma unroll
        for (int nf = 0; nf < 8; nf++) {
            int gucol = r0 + wn * 64 + nf * 8 + (lane & 3) * 2;
            float bg = gb[gucol], bu = gb[gucol + 1];
            int cl = wn * 32 + nf * 4 + (lane & 3);
#pragma unroll
            for (int rr = 0; rr < 2; rr++) {
                int r = wm * 32 + mf * 16 + (lane >> 2) + rr * 8;
                float gate = acc[mf][nf][rr * 2 + 0] + bg;
                float up   = acc[mf][nf][rr * 2 + 1] + bu;
                gate = fminf(gate, 7.0f);
                up = fminf(fmaxf(up, -7.0f), 7.0f);
                float sg = 1.0f / (1.0f + __expf(-1.702f * gate));
                float a = (up + 1.0f) * (gate * sg);
                stage[r * 72 + cl] = __half_as_ushort(__float2half_rn(a));
            }
        }
    __syncthreads();
    {
        int row = tid >> 1;
        if (row < valid) {
            size_t gbase = (size_t)(off + m0 + row) * D_INTER + (r0 >> 1) + (tid & 1) * 32;
            uint4* dh = (uint4*)(g_act + gbase);
            const uint4* shp = (const uint4*)(stage + row * 72 + (tid & 1) * 32);
#pragma unroll
            for (int i = 0; i < 4; i++) dh[i] = shp[i];
        }
    }
}

// ============================================================
// GEMM2 (single fp16 plane, B via cp.async from prequantized fp16)
// ============================================================
__global__ __launch_bounds__(256, 2) void gemm2_kernel(
    const float* __restrict__ dbias, float* __restrict__ out) {
    const int e  = blockIdx.y >> 3;
    const int r0 = (blockIdx.y & 7) << 7;
    const int m0 = blockIdx.x << 7;
    const int cnt = g_count[e];
    if (m0 >= cnt) return;
    const int valid = min(128, cnt - m0);
    const int off = g_off[e];
    extern __shared__ char smem[];
    const uint32_t sb = smem_u32(smem);
    const int tid = threadIdx.x, wid = tid >> 5, lane = tid & 31;
    const int wm = wid & 3, wn = wid >> 2;

    int* stok = (int*)(smem + SM_TOK);
    float* scoef = (float*)(smem + SM_COEF);
    if (tid < 128) {
        int mm = (tid < valid) ? tid : 0;
        stok[tid] = g_list[e][m0 + mm];
        scoef[tid] = g_coefs[e][m0 + mm];
    }
    __syncthreads();

    const int arow = tid >> 1, kh = (tid & 1) << 5;
    const int pr = off + m0 + ((arow < valid) ? arow : 0);
    const unsigned short* ah = g_act + (size_t)pr * D_INTER + kh;
    const unsigned short* bwp = g_dn16 + (size_t)(e * D_HIDDEN + r0 + arow) * D_INTER + kh;
    const uint32_t fbase = (uint32_t)arow << 7;
    const uint32_t frx = ((uint32_t)arow & 7u) << 4;
    uint32_t fo[4];
#pragma unroll
    for (int j = 0; j < 4; j++)
        fo[j] = fbase + ((((uint32_t)(kh + j * 8)) << 1) ^ frx);

    uint32_t aAddr[2], arx[2];
#pragma unroll
    for (int mf = 0; mf < 2; mf++) {
        int r = wm * 32 + mf * 16 + (lane & 15);
        aAddr[mf] = sb + ((uint32_t)r << 7);
        arx[mf] = ((uint32_t)r & 7u) << 4;
    }
    const uint32_t a_cb = (uint32_t)(lane >> 4) << 4;
    uint32_t bAddr[4], brxv[4];
#pragma unroll
    for (int g = 0; g < 4; g++) {
        int r = wn * 64 + g * 16 + ((lane >> 4) << 3) + (lane & 7);
        bAddr[g] = sb + SM_BB + ((uint32_t)r << 7);
        brxv[g] = ((uint32_t)r & 7u) << 4;
    }
    const uint32_t b_cb = ((uint32_t)(lane >> 3) & 1u) << 4;

    float acc[2][8][4];
#pragma unroll
    for (int mf = 0; mf < 2; mf++)
#pragma unroll
        for (int nf = 0; nf < 8; nf++)
#pragma unroll
            for (int j = 0; j < 4; j++) acc[mf][nf][j] = 0.0f;

#pragma unroll
    for (int j = 0; j < 4; j++) {
        CP16(sb + SM_AH + fo[j], ah + j * 8);
        CP16(sb + SM_BB + fo[j], bwp + j * 8);
    }
    CP_COMMIT();

    const int NKB = D_INTER / 64;
    for (int kb = 0; kb < NKB; kb++) {
        const uint32_t bo = (uint32_t)(kb & 1) * SM_BUF;
        CP_WAIT0();
        __syncthreads();
        if (kb + 1 < NKB) {
            const uint32_t bo2 = (uint32_t)((kb + 1) & 1) * SM_BUF;
#pragma unroll
            for (int j = 0; j < 4; j++) {
                CP16(sb + bo2 + SM_AH + fo[j], ah + (kb + 1) * 64 + j * 8);
                CP16(sb + bo2 + SM_BB + fo[j], bwp + (kb + 1) * 64 + j * 8);
            }
            CP_COMMIT();
        }
#pragma unroll
        for (int ks = 0; ks < 4; ks++) {
            uint32_t acol = (uint32_t)ks * 32 + a_cb;
            uint32_t bcol = (uint32_t)ks * 32 + b_cb;
            uint32_t Ah[2][4], Bf[4][4];
#pragma unroll
            for (int mf = 0; mf < 2; mf++)
                LDSM_X4(Ah[mf], aAddr[mf] + bo + SM_AH + (acol ^ arx[mf]));
#pragma unroll
            for (int g = 0; g < 4; g++) LDSM_X4(Bf[g], bAddr[g] + bo + (bcol ^ brxv[g]));
#pragma unroll
            for (int mf = 0; mf < 2; mf++)
#pragma unroll
                for (int nf = 0; nf < 8; nf++) {
                    uint32_t bb0 = Bf[nf >> 1][(nf & 1) * 2];
                    uint32_t bb1 = Bf[nf >> 1][(nf & 1) * 2 + 1];
                    MMAF16(acc[mf][nf], Ah[mf], bb0, bb1);
                }
        }
    }

    const float* db = dbias + (size_t)e * D_HIDDEN;
#pragma unroll
    for (int mf = 0; mf < 2; mf++)
#pragma unroll
        for (int nf = 0; nf < 8; nf++) {
            int gcol = r0 + wn * 64 + nf * 8 + (lane & 3) * 2;
            float b0 = db[gcol], b1 = db[gcol + 1];
#pragma unroll
            for (int rr = 0; rr < 2; rr++) {
                int m = wm * 32 + mf * 16 + (lane >> 2) + rr * 8;
                if (m < valid) {
                    float coef = scoef[m];
                    float* orow = out + (size_t)stok[m] * D_HIDDEN;
                    atomicAdd(orow + gcol,     coef * (acc[mf][nf][rr * 2 + 0] + b0));
                    atomicAdd(orow + gcol + 1, coef * (acc[mf][nf][rr * 2 + 1] + b1));
                }
            }
        }
}

// ============================================================
extern "C" void kernel_launch(void* const* d_in, const int* in_sizes, int n_in,
                              void* d_out, int out_size) {
    const float* x     = (const float*)d_in[0];
    const float* rw    = (const float*)d_in[1];
    const float* rb    = (const float*)d_in[2];
    const float* gbias = (const float*)d_in[3];
    const float* dbias = (const float*)d_in[4];
    const int*   gub   = (const int*)d_in[5];
    const int*   gus   = (const int*)d_in[6];
    const int*   dnb   = (const int*)d_in[7];
    const int*   dns   = (const int*)d_in[8];
    float* out = (float*)d_out;

    cudaFuncSetAttribute(gemm1_kernel, cudaFuncAttributeMaxDynamicSharedMemorySize, SM_TOTAL);
    cudaFuncSetAttribute(gemm2_kernel, cudaFuncAttributeMaxDynamicSharedMemorySize, SM_TOTAL);
    unsigned short* gu16; cudaGetSymbolAddress((void**)&gu16, g_gu16);
    unsigned short* dn16; cudaGetSymbolAddress((void**)&dn16, g_dn16);

    zero_kernel<<<(out_size + 255) / 256, 256>>>(out, out_size);
    prep_x_kernel<<<NTOK, 256>>>(x);
    // gu: 33.5M bytes / 4 bytes-per-thread / 256 = 32768 blocks; row = 512 bytes, 16 scale blocks? (32)
    prequant_kernel<<<32768, 256>>>(gub, gus, gu16, 512, 32);
    prequant_kernel<<<16384, 256>>>(dnb, dns, dn16, 2048, 128);
    router_kernel<<<NTOK / 8, 256>>>(x, rw, rb);
    compact_kernel<<<NE, 256>>>();
    offsets_kernel<<<1, 32>>>();
    gemm1_kernel<<<dim3(16, NE * 64), 256, SM_TOTAL>>>(gbias);
    gemm2_kernel<<<dim3(16, NE * 8), 256, SM_TOTAL>>>(dbias, out);
}

// round 16
// speedup vs baseline: 1.5541x; 1.0032x over previous
#include <cuda_runtime.h>
#include <cuda_fp16.h>
#include <math.h>
#include <stdint.h>

#define D_HIDDEN 1024
#define D_INTER  4096
#define NE       8
#define NTOK     2048
#define NPAIR    (NTOK * 2)
#define GU_ROWS  8192

// per-buffer: AH 16K | AL 16K | B 16K ; two buffers (stride 48K)
#define SM_AH    0
#define SM_AL    16384
#define SM_BB    32768
#define SM_BUF   49152
#define SM_TOK   98304
#define SM_COEF  98816
#define SM_TOTAL 99328

__device__ __forceinline__ uint32_t smem_u32(const void* p) {
    uint32_t a;
    asm("{ .reg .u64 t; cvta.to.shared.u64 t, %1; cvt.u32.u64 %0, t; }" : "=r"(a) : "l"(p));
    return a;
}
#define LDSM_X4(r, addr) \
    asm volatile("ldmatrix.sync.aligned.m8n8.x4.shared.b16 {%0,%1,%2,%3}, [%4];" \
        : "=r"((r)[0]), "=r"((r)[1]), "=r"((r)[2]), "=r"((r)[3]) : "r"(addr))
#define MMAF16(c, a, b0, b1) \
    asm volatile("mma.sync.aligned.m16n8k16.row.col.f32.f16.f16.f32 " \
        "{%0,%1,%2,%3}, {%4,%5,%6,%7}, {%8,%9}, {%0,%1,%2,%3};" \
        : "+f"((c)[0]), "+f"((c)[1]), "+f"((c)[2]), "+f"((c)[3]) \
        : "r"((a)[0]), "r"((a)[1]), "r"((a)[2]), "r"((a)[3]), "r"(b0), "r"(b1))
#define CP16(dst, src) \
    asm volatile("cp.async.cg.shared.global [%0], [%1], 16;" :: "r"(dst), "l"(src))
#define CP_COMMIT() asm volatile("cp.async.commit_group;" ::: "memory")
#define CP_WAIT0()  asm volatile("cp.async.wait_group 0;" ::: "memory")

// fp16 bits of {0,.5,1,1.5,2,3,4,6} and negatives
__device__ __constant__ unsigned short c_lut16[16] = {
    0x0000, 0x3800, 0x3C00, 0x3E00, 0x4000, 0x4200, 0x4400, 0x4600,
    0x8000, 0xB800, 0xBC00, 0xBE00, 0xC000, 0xC200, 0xC400, 0xC600};

__device__ int   g_top_idx[NTOK][2];
__device__ float g_top_w[NTOK][2];
__device__ int   g_count[NE];
__device__ int   g_off[NE];
__device__ int   g_list[NE][NTOK];
__device__ float g_coefs[NE][NTOK];
__device__ unsigned short g_x_h[(size_t)NTOK * D_HIDDEN];
__device__ unsigned short g_x_l[(size_t)NTOK * D_HIDDEN];
__device__ unsigned short g_act[(size_t)NPAIR * D_INTER];
__device__ unsigned short g_gu16[(size_t)NE * GU_ROWS * D_HIDDEN];   // 134 MB fp16 weights
__device__ unsigned short g_dn16[(size_t)NE * D_HIDDEN * D_INTER];   // 67 MB

__global__ void zero_kernel(float* __restrict__ out, int n) {
    int i = blockIdx.x * blockDim.x + threadIdx.x;
    if (i < n) out[i] = 0.0f;
}
__global__ void prep_x_kernel(const float* __restrict__ x) {
    int row = blockIdx.x;
    int c = threadIdx.x * 4;
    float4 f = *(const float4*)(x + (size_t)row * D_HIDDEN + c);
    float v[4] = {f.x, f.y, f.z, f.w};
    unsigned short h[4], l[4];
#pragma unroll
    for (int i = 0; i < 4; i++) {
        __half hh = __float2half_rn(v[i]);
        h[i] = __half_as_ushort(hh);
        l[i] = __half_as_ushort(__float2half_rn(v[i] - __half2float(hh)));
    }
    uint2 ph, pl;
    ph.x = (uint32_t)h[0] | ((uint32_t)h[1] << 16); ph.y = (uint32_t)h[2] | ((uint32_t)h[3] << 16);
    pl.x = (uint32_t)l[0] | ((uint32_t)l[1] << 16); pl.y = (uint32_t)l[2] | ((uint32_t)l[3] << 16);
    *(uint2*)(g_x_h + (size_t)row * D_HIDDEN + c) = ph;
    *(uint2*)(g_x_l + (size_t)row * D_HIDDEN + c) = pl;
}
// inflated int32 fp4-bytes + scales -> fp16 weights (8 elems/thread)
// byte-LUT (smem) + exact power-of-2 HMUL2
__global__ void prequant_kernel(const int* __restrict__ src, const int* __restrict__ scales,
                                unsigned short* __restrict__ dst, int bpr_b, int spr) {
    __shared__ uint32_t tbl[256];
    const int tid = threadIdx.x;
    {
        uint32_t lo = c_lut16[tid & 15], hi = c_lut16[(tid >> 4) & 15];
        tbl[tid] = lo | (hi << 16);
    }
    __syncthreads();
    size_t g = (size_t)blockIdx.x * 256 + tid;   // 4 inflated bytes -> 8 elems
    size_t row = (g * 4) / (size_t)bpr_b;
    int bcol = (int)((g * 4) % (size_t)bpr_b);
    const int4 q = *(const int4*)(src + row * bpr_b + bcol);
    int s = scales[row * spr + (bcol >> 4)];
    uint32_t sh = ((uint32_t)(s - 112) << 10);   // fp16 bits of 2^(s-127)
    __half2 sp = *(__half2*)&(uint32_t&)(sh = sh | (sh << 16));
    uint4 o;
    __half2 r0 = __hmul2(*(__half2*)&tbl[(uint32_t)q.x & 255u], sp);
    __half2 r1 = __hmul2(*(__half2*)&tbl[(uint32_t)q.y & 255u], sp);
    __half2 r2 = __hmul2(*(__half2*)&tbl[(uint32_t)q.z & 255u], sp);
    __half2 r3 = __hmul2(*(__half2*)&tbl[(uint32_t)q.w & 255u], sp);
    o.x = *(uint32_t*)&r0; o.y = *(uint32_t*)&r1;
    o.z = *(uint32_t*)&r2; o.w = *(uint32_t*)&r3;
    *(uint4*)(dst + g * 8) = o;
}
__global__ void router_kernel(const float* __restrict__ x,
                              const float* __restrict__ rw,
                              const float* __restrict__ rb) {
    int warp = threadIdx.x >> 5, lane = threadIdx.x & 31;
    int t = blockIdx.x * 8 + warp;
    if (t >= NTOK) return;
    float acc[NE];
#pragma unroll
    for (int e = 0; e < NE; e++) acc[e] = 0.0f;
    const float* xr = x + (size_t)t * D_HIDDEN;
    for (int k = lane; k < D_HIDDEN; k += 32) {
        float xv = xr[k];
#pragma unroll
        for (int e = 0; e < NE; e++) acc[e] += xv * rw[e * D_HIDDEN + k];
    }
#pragma unroll
    for (int e = 0; e < NE; e++)
#pragma unroll
        for (int o = 16; o > 0; o >>= 1) acc[e] += __shfl_xor_sync(0xffffffffu, acc[e], o);
    if (lane == 0) {
        float v[NE];
#pragma unroll
        for (int e = 0; e < NE; e++) v[e] = acc[e] + rb[e];
        int i0 = 0;
#pragma unroll
        for (int e = 1; e < NE; e++) if (v[e] > v[i0]) i0 = e;
        int i1 = -1;
#pragma unroll
        for (int e = 0; e < NE; e++) {
            if (e == i0) continue;
            if (i1 < 0 || v[e] > v[i1]) i1 = e;
        }
        float w1 = expf(v[i1] - v[i0]);
        float inv = 1.0f / (1.0f + w1);
        g_top_idx[t][0] = i0; g_top_idx[t][1] = i1;
        g_top_w[t][0] = inv;  g_top_w[t][1] = w1 * inv;
    }
}
__global__ void compact_kernel() {
    const int e = blockIdx.x, tid = threadIdx.x;
    __shared__ int scan[256];
    __shared__ int sbase;
    if (tid == 0) sbase = 0;
    __syncthreads();
    for (int c = 0; c < NTOK; c += 256) {
        int t = c + tid;
        int flag = (g_top_idx[t][0] == e) || (g_top_idx[t][1] == e);
        float coef = (g_top_idx[t][0] == e) ? g_top_w[t][0] : g_top_w[t][1];
        scan[tid] = flag;
        __syncthreads();
#pragma unroll
        for (int off = 1; off < 256; off <<= 1) {
            int v = (tid >= off) ? scan[tid - off] : 0;
            __syncthreads();
            scan[tid] += v;
            __syncthreads();
        }
        if (flag) {
            int pos = sbase + scan[tid] - 1;
            g_list[e][pos] = t; g_coefs[e][pos] = coef;
        }
        __syncthreads();
        if (tid == 0) sbase += scan[255];
        __syncthreads();
    }
    if (tid == 0) g_count[e] = sbase;
}
__global__ void offsets_kernel() {
    if (threadIdx.x == 0) {
        int r = 0;
#pragma unroll
        for (int e = 0; e < NE; e++) { g_off[e] = r; r += g_count[e]; }
    }
}

// ============================================================
// GEMM1: fp16 hi+lo planes, B via cp.async from prequantized fp16.
// 128x128 tile, BK=64, 8 warps (4M x 2N), warp 32x64, double-buffered.
// ============================================================
__global__ __launch_bounds__(256, 2) void gemm1_kernel(const float* __restrict__ gbias) {
    const int e  = blockIdx.y >> 6;
    const int r0 = (blockIdx.y & 63) << 7;
    const int m0 = blockIdx.x << 7;
    const int cnt = g_count[e];
    if (m0 >= cnt) return;
    const int valid = min(128, cnt - m0);
    const int off = g_off[e];
    extern __shared__ char smem[];
    const uint32_t sb = smem_u32(smem);
    const int tid = threadIdx.x, wid = tid >> 5, lane = tid & 31;
    const int wm = wid & 3, wn = wid >> 2;

    int* stok = (int*)(smem + SM_TOK);
    if (tid < 128) stok[tid] = g_list[e][m0 + (tid < valid ? tid : 0)];
    __syncthreads();

    const int arow = tid >> 1, kh = (tid & 1) << 5;
    const unsigned short* xh = g_x_h + (size_t)stok[arow] * D_HIDDEN + kh;
    const unsigned short* xl = g_x_l + (size_t)stok[arow] * D_HIDDEN + kh;
    const unsigned short* bwp = g_gu16 + (size_t)(e * GU_ROWS + r0 + arow) * D_HIDDEN + kh;
    const uint32_t fbase = (uint32_t)arow << 7;
    const uint32_t frx = ((uint32_t)arow & 7u) << 4;
    uint32_t fo[4];
#pragma unroll
    for (int j = 0; j < 4; j++)
        fo[j] = fbase + ((((uint32_t)(kh + j * 8)) << 1) ^ frx);

    uint32_t aAddr[2], arx[2];
#pragma unroll
    for (int mf = 0; mf < 2; mf++) {
        int r = wm * 32 + mf * 16 + (lane & 15);
        aAddr[mf] = sb + ((uint32_t)r << 7);
        arx[mf] = ((uint32_t)r & 7u) << 4;
    }
    const uint32_t a_cb = (uint32_t)(lane >> 4) << 4;
    uint32_t bAddr[4], brxv[4];
#pragma unroll
    for (int g = 0; g < 4; g++) {
        int r = wn * 64 + g * 16 + ((lane >> 4) << 3) + (lane & 7);
        bAddr[g] = sb + SM_BB + ((uint32_t)r << 7);
        brxv[g] = ((uint32_t)r & 7u) << 4;
    }
    const uint32_t b_cb = ((uint32_t)(lane >> 3) & 1u) << 4;

    float acc[2][8][4];
#pragma unroll
    for (int mf = 0; mf < 2; mf++)
#pragma unroll
        for (int nf = 0; nf < 8; nf++)
#pragma unroll
            for (int j = 0; j < 4; j++) acc[mf][nf][j] = 0.0f;

#pragma unroll
    for (int j = 0; j < 4; j++) {
        CP16(sb + SM_AH + fo[j], xh + j * 8);
        CP16(sb + SM_AL + fo[j], xl + j * 8);
        CP16(sb + SM_BB + fo[j], bwp + j * 8);
    }
    CP_COMMIT();

    const int NKB = D_HIDDEN / 64;
    for (int kb = 0; kb < NKB; kb++) {
        const uint32_t bo = (uint32_t)(kb & 1) * SM_BUF;
        CP_WAIT0();
        __syncthreads();
        if (kb + 1 < NKB) {
            const uint32_t bo2 = (uint32_t)((kb + 1) & 1) * SM_BUF;
#pragma unroll
            for (int j = 0; j < 4; j++) {
                CP16(sb + bo2 + SM_AH + fo[j], xh + (kb + 1) * 64 + j * 8);
                CP16(sb + bo2 + SM_AL + fo[j], xl + (kb + 1) * 64 + j * 8);
                CP16(sb + bo2 + SM_BB + fo[j], bwp + (kb + 1) * 64 + j * 8);
            }
            CP_COMMIT();
        }
#pragma unroll
        for (int ks = 0; ks < 4; ks++) {
            uint32_t acol = (uint32_t)ks * 32 + a_cb;
            uint32_t bcol = (uint32_t)ks * 32 + b_cb;
            uint32_t Ah[2][4], Al[2][4], Bf[4][4];
#pragma unroll
            for (int mf = 0; mf < 2; mf++) {
                LDSM_X4(Ah[mf], aAddr[mf] + bo + SM_AH + (acol ^ arx[mf]));
                LDSM_X4(Al[mf], aAddr[mf] + bo + SM_AL + (acol ^ arx[mf]));
            }
#pragma unroll
            for (int g = 0; g < 4; g++) LDSM_X4(Bf[g], bAddr[g] + bo + (bcol ^ brxv[g]));
#pragma unroll
            for (int mf = 0; mf < 2; mf++)
#pragma unroll
                for (int nf = 0; nf < 8; nf++) {
                    uint32_t bb0 = Bf[nf >> 1][(nf & 1) * 2];
                    uint32_t bb1 = Bf[nf >> 1][(nf & 1) * 2 + 1];
                    MMAF16(acc[mf][nf], Ah[mf], bb0, bb1);
                    MMAF16(acc[mf][nf], Al[mf], bb0, bb1);
                }
        }
    }
    __syncthreads();

    // epilogue: bias + SwiGLU -> stage -> single fp16 act plane
    const float* gb = gbias + (size_t)e * GU_ROWS;
    unsigned short* stage = (unsigned short*)smem;
#pragma unroll
    for (int mf = 0; mf < 2; mf++)
#pragma unroll
        for (int nf = 0; nf < 8; nf++) {
            int gucol = r0 + wn * 64 + nf * 8 + (lane & 3) * 2;
            float bg = gb[gucol], bu = gb[gucol + 1];
            int cl = wn * 32 + nf * 4 + (lane & 3);
#pragma unroll
            for (int rr = 0; rr < 2; rr++) {
                int r = wm * 32 + mf * 16 + (lane >> 2) + rr * 8;
                float gate = acc[mf][nf][rr * 2 + 0] + bg;
                float up   = acc[mf][nf][rr * 2 + 1] + bu;
                gate = fminf(gate, 7.0f);
                up = fminf(fmaxf(up, -7.0f), 7.0f);
                float sg = 1.0f / (1.0f + __expf(-1.702f * gate));
                float a = (up + 1.0f) * (gate * sg);
                stage[r * 72 + cl] = __half_as_ushort(__float2half_rn(a));
            }
        }
    __syncthreads();
    {
        int row = tid >> 1;
        if (row < valid) {
            size_t gbase = (size_t)(off + m0 + row) * D_INTER + (r0 >> 1) + (tid & 1) * 32;
            uint4* dh = (uint4*)(g_act + gbase);
            const uint4* shp = (const uint4*)(stage + row * 72 + (tid & 1) * 32);
#pragma unroll
            for (int i = 0; i < 4; i++) dh[i] = shp[i];
        }
    }
}

// ============================================================
// GEMM2 (single fp16 plane, B via cp.async from prequantized fp16)
// ============================================================
__global__ __launch_bounds__(256, 2) void gemm2_kernel(
    const float* __restrict__ dbias, float* __restrict__ out) {
    const int e  = blockIdx.y >> 3;
    const int r0 = (blockIdx.y & 7) << 7;
    const int m0 = blockIdx.x << 7;
    const int cnt = g_count[e];
    if (m0 >= cnt) return;
    const int valid = min(128, cnt - m0);
    const int off = g_off[e];
    extern __shared__ char smem[];
    const uint32_t sb = smem_u32(smem);
    const int tid = threadIdx.x, wid = tid >> 5, lane = tid & 31;
    const int wm = wid & 3, wn = wid >> 2;

    int* stok = (int*)(smem + SM_TOK);
    float* scoef = (float*)(smem + SM_COEF);
    if (tid < 128) {
        int mm = (tid < valid) ? tid : 0;
        stok[tid] = g_list[e][m0 + mm];
        scoef[tid] = g_coefs[e][m0 + mm];
    }
    __syncthreads();

    const int arow = tid >> 1, kh = (tid & 1) << 5;
    const int pr = off + m0 + ((arow < valid) ? arow : 0);
    const unsigned short* ah = g_act + (size_t)pr * D_INTER + kh;
    const unsigned short* bwp = g_dn16 + (size_t)(e * D_HIDDEN + r0 + arow) * D_INTER + kh;
    const uint32_t fbase = (uint32_t)arow << 7;
    const uint32_t frx = ((uint32_t)arow & 7u) << 4;
    uint32_t fo[4];
#pragma unroll
    for (int j = 0; j < 4; j++)
        fo[j] = fbase + ((((uint32_t)(kh + j * 8)) << 1) ^ frx);

    uint32_t aAddr[2], arx[2];
#pragma unroll
    for (int mf = 0; mf < 2; mf++) {
        int r = wm * 32 + mf * 16 + (lane & 15);
        aAddr[mf] = sb + ((uint32_t)r << 7);
        arx[mf] = ((uint32_t)r & 7u) << 4;
    }
    const uint32_t a_cb = (uint32_t)(lane >> 4) << 4;
    uint32_t bAddr[4], brxv[4];
#pragma unroll
    for (int g = 0; g < 4; g++) {
        int r = wn * 64 + g * 16 + ((lane >> 4) << 3) + (lane & 7);
        bAddr[g] = sb + SM_BB + ((uint32_t)r << 7);
        brxv[g] = ((uint32_t)r & 7u) << 4;
    }
    const uint32_t b_cb = ((uint32_t)(lane >> 3) & 1u) << 4;

    float acc[2][8][4];
#pragma unroll
    for (int mf = 0; mf < 2; mf++)
#pragma unroll
        for (int nf = 0; nf < 8; nf++)
#pragma unroll
            for (int j = 0; j < 4; j++) acc[mf][nf][j] = 0.0f;

#pragma unroll
    for (int j = 0; j < 4; j++) {
        CP16(sb + SM_AH + fo[j], ah + j * 8);
        CP16(sb + SM_BB + fo[j], bwp + j * 8);
    }
    CP_COMMIT();

    const int NKB = D_INTER / 64;
    for (int kb = 0; kb < NKB; kb++) {
        const uint32_t bo = (uint32_t)(kb & 1) * SM_BUF;
        CP_WAIT0();
        __syncthreads();
        if (kb + 1 < NKB) {
            const uint32_t bo2 = (uint32_t)((kb + 1) & 1) * SM_BUF;
#pragma unroll
            for (int j = 0; j < 4; j++) {
                CP16(sb + bo2 + SM_AH + fo[j], ah + (kb + 1) * 64 + j * 8);
                CP16(sb + bo2 + SM_BB + fo[j], bwp + (kb + 1) * 64 + j * 8);
            }
            CP_COMMIT();
        }
#pragma unroll
        for (int ks = 0; ks < 4; ks++) {
            uint32_t acol = (uint32_t)ks * 32 + a_cb;
            uint32_t bcol = (uint32_t)ks * 32 + b_cb;
            uint32_t Ah[2][4], Bf[4][4];
#pragma unroll
            for (int mf = 0; mf < 2; mf++)
                LDSM_X4(Ah[mf], aAddr[mf] + bo + SM_AH + (acol ^ arx[mf]));
#pragma unroll
            for (int g = 0; g < 4; g++) LDSM_X4(Bf[g], bAddr[g] + bo + (bcol ^ brxv[g]));
#pragma unroll
            for (int mf = 0; mf < 2; mf++)
#pragma unroll
                for (int nf = 0; nf < 8; nf++) {
                    uint32_t bb0 = Bf[nf >> 1][(nf & 1) * 2];
                    uint32_t bb1 = Bf[nf >> 1][(nf & 1) * 2 + 1];
                    MMAF16(acc[mf][nf], Ah[mf], bb0, bb1);
                }
        }
    }

    const float* db = dbias + (size_t)e * D_HIDDEN;
#pragma unroll
    for (int mf = 0; mf < 2; mf++)
#pragma unroll
        for (int nf = 0; nf < 8; nf++) {
            int gcol = r0 + wn * 64 + nf * 8 + (lane & 3) * 2;
            float b0 = db[gcol], b1 = db[gcol + 1];
#pragma unroll
            for (int rr = 0; rr < 2; rr++) {
                int m = wm * 32 + mf * 16 + (lane >> 2) + rr * 8;
                if (m < valid) {
                    float coef = scoef[m];
                    float* orow = out + (size_t)stok[m] * D_HIDDEN;
                    atomicAdd(orow + gcol,     coef * (acc[mf][nf][rr * 2 + 0] + b0));
                    atomicAdd(orow + gcol + 1, coef * (acc[mf][nf][rr * 2 + 1] + b1));
                }
            }
        }
}

// ============================================================
extern "C" void kernel_launch(void* const* d_in, const int* in_sizes, int n_in,
                              void* d_out, int out_size) {
    const float* x     = (const float*)d_in[0];
    const float* rw    = (const float*)d_in[1];
    const float* rb    = (const float*)d_in[2];
    const float* gbias = (const float*)d_in[3];
    const float* dbias = (const float*)d_in[4];
    const int*   gub   = (const int*)d_in[5];
    const int*   gus   = (const int*)d_in[6];
    const int*   dnb   = (const int*)d_in[7];
    const int*   dns   = (const int*)d_in[8];
    float* out = (float*)d_out;

    cudaFuncSetAttribute(gemm1_kernel, cudaFuncAttributeMaxDynamicSharedMemorySize, SM_TOTAL);
    cudaFuncSetAttribute(gemm2_kernel, cudaFuncAttributeMaxDynamicSharedMemorySize, SM_TOTAL);
    unsigned short* gu16; cudaGetSymbolAddress((void**)&gu16, g_gu16);
    unsigned short* dn16; cudaGetSymbolAddress((void**)&dn16, g_dn16);

    zero_kernel<<<(out_size + 255) / 256, 256>>>(out, out_size);
    prep_x_kernel<<<NTOK, 256>>>(x);
    prequant_kernel<<<32768, 256>>>(gub, gus, gu16, 512, 32);
    prequant_kernel<<<16384, 256>>>(dnb, dns, dn16, 2048, 128);
    router_kernel<<<NTOK / 8, 256>>>(x, rw, rb);
    compact_kernel<<<NE, 256>>>();
    offsets_kernel<<<1, 32>>>();
    gemm1_kernel<<<dim3(16, NE * 64), 256, SM_TOTAL>>>(gbias);
    gemm2_kernel<<<dim3(16, NE * 8), 256, SM_TOTAL>>>(dbias, out);
}